// round 8
// baseline (speedup 1.0000x reference)
#include <cuda_runtime.h>
#include <cstdint>
#include <math.h>

#define HH 128
#define WW 128
#define HW (128*128)
#define FFT_T 1024

typedef unsigned long long u64;

// ---------------- scratch (device globals; no allocation) ----------------
__device__ float g_feat0[2*128*HW];
__device__ float g_feat1[2*64*HW];
__device__ float g_feat2[2*64*HW];
__device__ float g_om  [2*27*HW];
__device__ float g_d2  [2*64*HW];
__device__ float g_dp  [4*2*64*HW];   // dcn split partials

__device__ __forceinline__ int brev7(int v) { return (int)(__brev((unsigned)v) >> 25); }

// ---------------- packed fp32x2 helpers (sm_103a FFMA2) ----------------
__device__ __forceinline__ u64 pack2(float v) {
    u64 r; asm("mov.b64 %0, {%1, %1};" : "=l"(r) : "f"(v)); return r;
}
__device__ __forceinline__ u64 pack_pair(float lo, float hi) {
    u64 r; asm("mov.b64 %0, {%1, %2};" : "=l"(r) : "f"(lo), "f"(hi)); return r;
}
__device__ __forceinline__ void unpack2(u64 v, float& lo, float& hi) {
    asm("mov.b64 {%0, %1}, %2;" : "=f"(lo), "=f"(hi) : "l"(v));
}
__device__ __forceinline__ void fma2(u64& d, u64 a, u64 b) {
    asm("fma.rn.f32x2 %0, %1, %2, %0;" : "+l"(d) : "l"(a), "l"(b));
}

// ---------------- cp.async helpers ----------------
__device__ __forceinline__ uint32_t smem_u32(const void* p) {
    uint32_t a;
    asm("{ .reg .u64 t; cvta.to.shared.u64 t, %1; cvt.u32.u64 %0, t; }"
        : "=r"(a) : "l"(p));
    return a;
}
__device__ __forceinline__ void cp_async4(uint32_t saddr, const void* gaddr, int srcsize) {
    asm volatile("cp.async.ca.shared.global [%0], [%1], 4, %2;"
                 :: "r"(saddr), "l"(gaddr), "r"(srcsize));
}
#define CP_COMMIT() asm volatile("cp.async.commit_group;")
#define CP_WAIT(N)  asm volatile("cp.async.wait_group %0;" :: "n"(N))

// =====================================================================
// Kernel 1: packed FFT (z = x + i*x_ref), DIF fwd / DIT inv.
// Fused radix-2 stage pairs: 4 sync points per 1D pass instead of 7.
// Permutation identical to sequential radix-2 (bit reversal).
// =====================================================================
template<int STEP>
__device__ __forceinline__ void fft_dif(float* sre, float* sim,
                                        const float* ctab, const float* stab)
{
#pragma unroll
    for (int fp = 0; fp < 3; ++fp) {
        int s  = 6 - 2*fp;          // 6,4,2
        int mh = 1 << (s-1);
        for (int t = threadIdx.x; t < 4096; t += FFT_T) {
            int O = t >> 5, g = t & 31;
            int pos = g & (mh-1);
            int i = ((g >> (s-1)) << (s+1)) + pos;
            int base = (STEP == 1) ? O*128 + i : i*128 + O;
            int d1 = mh*STEP, d2 = 2*mh*STEP, d3 = 3*mh*STEP;
            float a0r=sre[base],    a0i=sim[base];
            float a1r=sre[base+d1], a1i=sim[base+d1];
            float a2r=sre[base+d2], a2i=sim[base+d2];
            float a3r=sre[base+d3], a3i=sim[base+d3];
            int r0 = pos << (6-s);
            float c0=ctab[r0], s0=stab[r0];
            // stage s: pairs (0,2) and (1,3); twiddle for (1,3) = W^{r0+32} = W^{r0}*(-i)
            float t0r=a0r+a2r, t0i=a0i+a2i;
            float e2r=a0r-a2r, e2i=a0i-a2i;
            float u2r=c0*e2r - s0*e2i, u2i=c0*e2i + s0*e2r;
            float t1r=a1r+a3r, t1i=a1i+a3i;
            float e3r=a1r-a3r, e3i=a1i-a3i;
            float u3r=s0*e3r + c0*e3i, u3i=s0*e3i - c0*e3r;
            // stage s-1: both pairs use rr = pos << (7-s)
            int rr = pos << (7-s);
            float c1=ctab[rr], s1=stab[rr];
            sre[base]    = t0r+t1r;           sim[base]    = t0i+t1i;
            float f1r=t0r-t1r, f1i=t0i-t1i;
            sre[base+d1] = c1*f1r - s1*f1i;   sim[base+d1] = c1*f1i + s1*f1r;
            sre[base+d2] = u2r+u3r;           sim[base+d2] = u2i+u3i;
            float f3r=u2r-u3r, f3i=u2i-u3i;
            sre[base+d3] = c1*f3r - s1*f3i;   sim[base+d3] = c1*f3i + s1*f3r;
        }
        __syncthreads();
    }
    // final stage 0 (twiddle = 1)
    for (int t = threadIdx.x; t < 8192; t += FFT_T) {
        int O = t >> 6, j = t & 63;
        int base = (STEP == 1) ? O*128 + 2*j : (2*j)*128 + O;
        float ar=sre[base], ai=sim[base];
        float br=sre[base+STEP], bi=sim[base+STEP];
        sre[base]=ar+br;      sim[base]=ai+bi;
        sre[base+STEP]=ar-br; sim[base+STEP]=ai-bi;
    }
    __syncthreads();
}

template<int STEP>
__device__ __forceinline__ void fft_dit(float* sre, float* sim,
                                        const float* ctab, const float* stab)
{
    // stage 0 (twiddle = 1)
    for (int t = threadIdx.x; t < 8192; t += FFT_T) {
        int O = t >> 6, j = t & 63;
        int base = (STEP == 1) ? O*128 + 2*j : (2*j)*128 + O;
        float ar=sre[base], ai=sim[base];
        float br=sre[base+STEP], bi=sim[base+STEP];
        sre[base]=ar+br;      sim[base]=ai+bi;
        sre[base+STEP]=ar-br; sim[base+STEP]=ai-bi;
    }
    __syncthreads();
#pragma unroll
    for (int fp = 0; fp < 3; ++fp) {
        int s = 1 + 2*fp;           // 1,3,5
        int m = 1 << s;
        for (int t = threadIdx.x; t < 4096; t += FFT_T) {
            int O = t >> 5, g = t & 31;
            int pos = g & (m-1);
            int i = ((g >> s) << (s+2)) + pos;
            int base = (STEP == 1) ? O*128 + i : i*128 + O;
            int d1 = m*STEP, d2 = 2*m*STEP, d3 = 3*m*STEP;
            float a0r=sre[base],    a0i=sim[base];
            float a1r=sre[base+d1], a1i=sim[base+d1];
            float a2r=sre[base+d2], a2i=sim[base+d2];
            float a3r=sre[base+d3], a3i=sim[base+d3];
            int r = pos << (6-s);
            float cw=ctab[r], sw=-stab[r];     // W^{-r}
            // stage s
            float t1r = cw*a1r - sw*a1i, t1i = cw*a1i + sw*a1r;
            float q0r = a0r+t1r, q0i = a0i+t1i;
            float q1r = a0r-t1r, q1i = a0i-t1i;
            float t3r = cw*a3r - sw*a3i, t3i = cw*a3i + sw*a3r;
            float q2r = a2r+t3r, q2i = a2i+t3i;
            float q3r = a2r-t3r, q3i = a2i-t3i;
            // stage s+1: (q0,q2) uses W^{-r2}; (q1,q3) uses W^{-(r2+32)} = W^{-r2}*(+i)
            int r2 = pos << (5-s);
            float c2=ctab[r2], s2=-stab[r2];
            float u2r = c2*q2r - s2*q2i, u2i = c2*q2i + s2*q2r;
            sre[base]    = q0r+u2r; sim[base]    = q0i+u2i;
            sre[base+d2] = q0r-u2r; sim[base+d2] = q0i-u2i;
            float u3r = -s2*q3r - c2*q3i, u3i = -s2*q3i + c2*q3r;
            sre[base+d1] = q1r+u3r; sim[base+d1] = q1i+u3i;
            sre[base+d3] = q1r-u3r; sim[base+d3] = q1i-u3i;
        }
        __syncthreads();
    }
}

__global__ __launch_bounds__(FFT_T) void fft_phase_kernel(
    const float* __restrict__ x, const float* __restrict__ xref,
    const float* __restrict__ amp, float* __restrict__ feat0)
{
    extern __shared__ float sm[];
    float* sre = sm;
    float* sim = sm + HW;
    __shared__ float ctab[64], stab[64];

    int bc = blockIdx.x;
    const float* srcx = x    + (size_t)bc * HW;
    const float* srcr = xref + (size_t)bc * HW;
    const float* ampp = amp  + (size_t)bc * (HH * 65);
    int tid = threadIdx.x;

    if (tid < 64) {
        float s, c;
        sincospif(-(float)tid / 64.0f, &s, &c);
        ctab[tid] = c; stab[tid] = s;
    }

    for (int i = tid; i < HW; i += FFT_T) {
        sre[i] = srcx[i];
        sim[i] = srcr[i];
    }
    __syncthreads();

    fft_dif<1>(sre, sim, ctab, stab);     // rows
    fft_dif<128>(sre, sim, ctab, stab);   // cols

    // spectral op in bit-reversed coordinates, Hermitian pair processing
    for (int i = tid; i < HW; i += FFT_T) {
        int hr = i >> 7, wr = i & 127;
        int h = brev7(hr), w = brev7(wr);
        int hm = (128 - h) & 127, wm = (128 - w) & 127;
        int pi = (brev7(hm) << 7) | brev7(wm);
        if (i > pi) continue;

        float Zr0 = sre[i],  Zi0 = sim[i];
        float Zr1 = sre[pi], Zi1 = sim[pi];

        float fxr = 0.5f * (Zr0 + Zr1), fxi = 0.5f * (Zi0 - Zi1);
        float frr = 0.5f * (Zi0 + Zi1), fri = 0.5f * (Zr1 - Zr0);

        float m2x = fxr * fxr + fxi * fxi;
        float uxr = 1.f, uxi = 0.f;
        if (m2x > 0.f) { float iv = rsqrtf(m2x); uxr = fxr * iv; uxi = fxi * iv; }
        float m2r = frr * frr + fri * fri;
        float urr = 1.f, uri = 0.f;
        if (m2r > 0.f) { float iv = rsqrtf(m2r); urr = frr * iv; uri = fri * iv; }

        float Gxr, Gxi, Grr, Gri;
        if (w == 0 || w == 64) {
            float a0 = ampp[h * 65 + w];
            float a1 = ampp[hm * 65 + w];
            float ap = 0.5f * (a0 + a1), am = 0.5f * (a0 - a1);
            Gxr = ap * uxr; Gxi = am * uxi;
            Grr = ap * urr; Gri = am * uri;
        } else {
            float a = (w < 64) ? ampp[h * 65 + w] : ampp[hm * 65 + (128 - w)];
            Gxr = a * uxr; Gxi = a * uxi;
            Grr = a * urr; Gri = a * uri;
        }

        sre[i]  = Gxr - Gri;  sim[i]  = Gxi + Grr;
        sre[pi] = Gxr + Gri;  sim[pi] = Grr - Gxi;
    }
    __syncthreads();

    fft_dit<1>(sre, sim, ctab, stab);
    fft_dit<128>(sre, sim, ctab, stab);

    int b  = bc >> 6;
    int ch = bc & 63;
    float* dstx = feat0 + ((size_t)(b * 128 + ch)) * HW;
    float* dstr = feat0 + ((size_t)(b * 128 + 64 + ch)) * HW;
    const float scale = 1.0f / 16384.0f;
    for (int i = tid; i < HW; i += FFT_T) {
        dstx[i] = sre[i] * scale;
        dstr[i] = sim[i] * scale;
    }
}

// =====================================================================
// Kernel 2 (v7): 3x3 conv, packed f32x2, 256 thr (32x8), tile 32x8,
// 1 row/thread, CB=16, cp.async double buffering. Small footprint ->
// 3-4 blocks/SM, grids >= 256.
// =====================================================================
template<bool DO_LRELU>
__global__ __launch_bounds__(256) void conv3x3_v7(
    const float* __restrict__ in1, int Cin1,
    const float* __restrict__ in2, int Cin2,
    const float* __restrict__ wgt, const float* __restrict__ bias,
    float* __restrict__ out, int Cout, int nblk)
{
    constexpr int CB = 16;
    constexpr int CIN_BLK = 4;
    constexpr int TROW = 10;                     // 8 out rows + 2 halo
    constexpr int TELEM = CIN_BLK * TROW * 34;   // 1360
    constexpr int WELEM = CIN_BLK * 9 * CB;      // 576

    __shared__ __align__(16) float tbuf[2][TELEM];
    __shared__ __align__(16) float wbuf[2][WELEM];

    int tid = threadIdx.y * 32 + threadIdx.x;
    int b   = blockIdx.z / nblk;
    int co0 = (blockIdx.z % nblk) * CB;
    int ty0 = blockIdx.y * 8;
    int tx0 = blockIdx.x * 32;
    int tx = threadIdx.x, ty = threadIdx.y;   // ty 0..7
    int Cin = Cin1 + Cin2;
    int nchunks = Cin / CIN_BLK;

    uint32_t tb_s0 = smem_u32(&tbuf[0][0]);
    uint32_t tb_s1 = smem_u32(&tbuf[1][0]);
    uint32_t wb_s0 = smem_u32(&wbuf[0][0]);
    uint32_t wb_s1 = smem_u32(&wbuf[1][0]);

    u64 a0[8];
#pragma unroll
    for (int o = 0; o < 8; ++o) a0[o] = 0ULL;

    auto stage = [&](int cin0, uint32_t tb_s, uint32_t wb_s) {
        for (int i = tid; i < TELEM; i += 256) {
            int c = i / (TROW * 34); int rem = i - c * (TROW * 34);
            int r = rem / 34; int col = rem - r * 34;
            int cin = cin0 + c;
            const float* src = (cin < Cin1)
                ? in1 + ((size_t)(b * Cin1 + cin)) * HW
                : in2 + ((size_t)(b * Cin2 + cin - Cin1)) * HW;
            int gy = ty0 - 1 + r, gx = tx0 - 1 + col;
            bool inb = ((unsigned)gy < 128u) && ((unsigned)gx < 128u);
            int cy = min(max(gy, 0), 127), cx = min(max(gx, 0), 127);
            cp_async4(tb_s + i * 4, src + cy * 128 + cx, inb ? 4 : 0);
        }
        for (int i = tid; i < WELEM; i += 256) {
            int c = i / (9 * CB); int rem = i - c * (9 * CB);
            int k = rem / CB; int o = rem - k * CB;
            int co = min(co0 + o, Cout - 1);
            cp_async4(wb_s + i * 4, &wgt[((size_t)co * Cin + cin0 + c) * 9 + k], 4);
        }
        CP_COMMIT();
    };

    stage(0, tb_s0, wb_s0);

    for (int chunk = 0; chunk < nchunks; ++chunk) {
        int cur = chunk & 1;
        bool hasnext = (chunk + 1 < nchunks);
        if (hasnext)
            stage((chunk + 1) * CIN_BLK, cur ? tb_s0 : tb_s1, cur ? wb_s0 : wb_s1);
        if (hasnext) { CP_WAIT(1); } else { CP_WAIT(0); }
        __syncthreads();

        const float* tb = tbuf[cur];
        const ulonglong2* wb2 = reinterpret_cast<const ulonglong2*>(wbuf[cur]);
#pragma unroll
        for (int c = 0; c < CIN_BLK; ++c) {
            const float* tp = tb + c * (TROW * 34) + ty * 34 + tx;
#pragma unroll
            for (int k = 0; k < 9; ++k) {
                int kyy = k / 3, kxx = k - kyy * 3;
                u64 v0 = pack2(tp[kyy * 34 + kxx]);
                const ulonglong2* wp = wb2 + (c * 9 + k) * 4;
#pragma unroll
                for (int j = 0; j < 4; ++j) {
                    ulonglong2 wv = wp[j];
                    fma2(a0[2*j],   wv.x, v0);
                    fma2(a0[2*j+1], wv.y, v0);
                }
            }
        }
        __syncthreads();
    }

#pragma unroll
    for (int p = 0; p < 8; ++p) {
        float rlo, rhi;
        unpack2(a0[p], rlo, rhi);
#pragma unroll
        for (int e = 0; e < 2; ++e) {
            int o = 2 * p + e;
            if (co0 + o >= Cout) continue;
            float v = (e ? rhi : rlo) + __ldg(&bias[co0 + o]);
            if (DO_LRELU) v = v >= 0.f ? v : 0.1f * v;
            size_t base = ((size_t)(b * Cout + co0 + o)) * HW;
            out[base + (size_t)(ty0 + ty) * 128 + tx0 + tx] = v;
        }
    }
}

// =====================================================================
// Kernel 3a: dcn partial — 16 input channels per block, k-outer loop,
// accumulates all 64 couts in registers, writes partial sums.
// =====================================================================
__global__ __launch_bounds__(256) void dcn_part(
    const float* __restrict__ x, const float* __restrict__ om,
    const float* __restrict__ wd, float* __restrict__ part, int cin0)
{
    __shared__ __align__(16) float wdsm[16 * 9 * 64];   // [c][k][o]

    int t = threadIdx.x;
    int b = blockIdx.z;
    int h = blockIdx.y * 16 + (t >> 4);
    int w = blockIdx.x * 16 + (t & 15);

    for (int i = t; i < 16 * 576; i += 256) {
        int c = i / 576; int rem = i - c * 576;
        int k = rem >> 6, o = rem & 63;
        wdsm[i] = wd[((size_t)o * 64 + cin0 + c) * 9 + k];
    }
    __syncthreads();

    const float* omb = om + (size_t)b * 27 * HW;
    int pix = h * 128 + w;

    u64 acc[32];
#pragma unroll
    for (int o = 0; o < 32; ++o) acc[o] = 0ULL;

    const float* xb = x + (size_t)b * 64 * HW + (size_t)cin0 * HW;

#pragma unroll
    for (int k = 0; k < 9; ++k) {
        float dy = omb[(size_t)(2 * k) * HW + pix];
        float dx = omb[(size_t)(2 * k + 1) * HW + pix];
        float mv = omb[(size_t)(18 + k) * HW + pix];
        float mk = 1.0f / (1.0f + expf(-mv));
        float py = (float)(h + k / 3 - 1) + dy;
        float px = (float)(w + k % 3 - 1) + dx;
        float fy = floorf(py), fx = floorf(px);
        int y0 = (int)fy, x0 = (int)fx;
        float wyy = py - fy, wxx = px - fx;
        int y1 = y0 + 1, x1 = x0 + 1;
        int cy0 = min(max(y0, 0), 127), cy1 = min(max(y1, 0), 127);
        int cx0 = min(max(x0, 0), 127), cx1 = min(max(x1, 0), 127);
        bool vy0 = (unsigned)y0 < 128u, vy1 = (unsigned)y1 < 128u;
        bool vx0 = (unsigned)x0 < 128u, vx1 = (unsigned)x1 < 128u;
        int a00 = cy0 * 128 + cx0, a01 = cy0 * 128 + cx1;
        int a10 = cy1 * 128 + cx0, a11 = cy1 * 128 + cx1;
        bool v00 = vy0 && vx0, v01 = vy0 && vx1, v10 = vy1 && vx0, v11 = vy1 && vx1;

        for (int c = 0; c < 16; ++c) {
            const float* xc = xb + (size_t)c * HW;
            float g00 = v00 ? __ldg(xc + a00) : 0.f;
            float g01 = v01 ? __ldg(xc + a01) : 0.f;
            float g10 = v10 ? __ldg(xc + a10) : 0.f;
            float g11 = v11 ? __ldg(xc + a11) : 0.f;
            float top = g00 + (g01 - g00) * wxx;
            float bot = g10 + (g11 - g10) * wxx;
            u64 ss = pack2((top + (bot - top) * wyy) * mk);
            const ulonglong2* wp = reinterpret_cast<const ulonglong2*>(wdsm + (c * 9 + k) * 64);
#pragma unroll
            for (int j = 0; j < 16; ++j) {
                ulonglong2 wv = wp[j];
                fma2(acc[2*j],   wv.x, ss);
                fma2(acc[2*j+1], wv.y, ss);
            }
        }
    }

    float* pb = part + (size_t)b * 64 * HW;
#pragma unroll
    for (int p = 0; p < 32; ++p) {
        float lo, hi;
        unpack2(acc[p], lo, hi);
        pb[(size_t)(2*p) * HW + pix]     = lo;
        pb[(size_t)(2*p+1) * HW + pix]   = hi;
    }
}

// =====================================================================
// Kernel 3b: dcn epilogue — sum 4 partials + bias + lrelu, fused 1x1 + lrelu.
// =====================================================================
__global__ __launch_bounds__(256) void dcn_epilogue(
    const float* __restrict__ dp,
    const float* __restrict__ bd,
    const float* __restrict__ w1, const float* __restrict__ b1,
    float* __restrict__ out)
{
    __shared__ __align__(16) float w1sm[64 * 64];   // [c][o]
    const size_t SPLIT = (size_t)2 * 64 * HW;

    int t = threadIdx.x;
    int b = blockIdx.z;
    int h = blockIdx.y * 16 + (t >> 4);
    int w = blockIdx.x * 16 + (t & 15);

    for (int i = t; i < 4096; i += 256) {
        int c = i >> 6, o = i & 63;
        w1sm[i] = w1[o * 64 + c];
    }
    __syncthreads();

    int pix = h * 128 + w;
    size_t boff = (size_t)b * 64 * HW;

    float av[64];
#pragma unroll
    for (int o = 0; o < 64; ++o) {
        size_t idx = boff + (size_t)o * HW + pix;
        float v = dp[idx] + dp[SPLIT + idx] + dp[2*SPLIT + idx] + dp[3*SPLIT + idx]
                + __ldg(&bd[o]);
        av[o] = v >= 0.f ? v : 0.1f * v;
    }

    float* outb = out + boff;
#pragma unroll
    for (int og = 0; og < 4; ++og) {
        u64 acc2[8];
#pragma unroll
        for (int j = 0; j < 8; ++j)
            acc2[j] = pack_pair(__ldg(&b1[og*16 + 2*j]), __ldg(&b1[og*16 + 2*j + 1]));
        for (int c = 0; c < 64; ++c) {
            u64 vv = pack2(av[c]);
            const ulonglong2* wp = reinterpret_cast<const ulonglong2*>(w1sm + c * 64 + og * 16);
#pragma unroll
            for (int j = 0; j < 4; ++j) {
                ulonglong2 wv = wp[j];
                fma2(acc2[2*j],   wv.x, vv);
                fma2(acc2[2*j+1], wv.y, vv);
            }
        }
#pragma unroll
        for (int j = 0; j < 8; ++j) {
            float lo, hi;
            unpack2(acc2[j], lo, hi);
            lo = lo >= 0.f ? lo : 0.1f * lo;
            hi = hi >= 0.f ? hi : 0.1f * hi;
            outb[(size_t)(og * 16 + 2*j) * HW + pix]     = lo;
            outb[(size_t)(og * 16 + 2*j + 1) * HW + pix] = hi;
        }
    }
}

// =====================================================================
// launch
// =====================================================================
extern "C" void kernel_launch(void* const* d_in, const int* in_sizes, int n_in,
                              void* d_out, int out_size)
{
    const float* x       = (const float*)d_in[0];
    const float* x_ref   = (const float*)d_in[1];
    const float* amp     = (const float*)d_in[2];
    const float* new_inp = (const float*)d_in[3];
    const float* w_off1  = (const float*)d_in[4];
    const float* b_off1  = (const float*)d_in[5];
    const float* w_off2  = (const float*)d_in[6];
    const float* b_off2  = (const float*)d_in[7];
    const float* w_om    = (const float*)d_in[8];
    const float* b_om    = (const float*)d_in[9];
    const float* w_dcn   = (const float*)d_in[10];
    const float* b_dcn   = (const float*)d_in[11];
    const float* w_1x1   = (const float*)d_in[12];
    const float* b_1x1   = (const float*)d_in[13];
    const float* w_3x3   = (const float*)d_in[14];
    const float* b_3x3   = (const float*)d_in[15];
    float* out = (float*)d_out;

    float *feat0, *feat1, *feat2, *omb, *d2, *dp;
    cudaGetSymbolAddress((void**)&feat0, g_feat0);
    cudaGetSymbolAddress((void**)&feat1, g_feat1);
    cudaGetSymbolAddress((void**)&feat2, g_feat2);
    cudaGetSymbolAddress((void**)&omb,   g_om);
    cudaGetSymbolAddress((void**)&d2,    g_d2);
    cudaGetSymbolAddress((void**)&dp,    g_dp);

    cudaFuncSetAttribute(fft_phase_kernel,
                         cudaFuncAttributeMaxDynamicSharedMemorySize, 131072);

    const size_t SPLIT = (size_t)2 * 64 * HW;

    // 1. packed FFT phase/amplitude recombination -> feat0
    fft_phase_kernel<<<128, FFT_T, 131072>>>(x, x_ref, amp, feat0);

    dim3 cblk(32, 8);

    // 2. conv_off1: 128 -> 64, lrelu  (512 blocks)
    conv3x3_v7<true><<<dim3(4, 16, 8), cblk>>>(
        feat0, 128, (const float*)nullptr, 0, w_off1, b_off1, feat1, 64, 4);

    // 3. conv_off2: 64 -> 64, lrelu
    conv3x3_v7<true><<<dim3(4, 16, 8), cblk>>>(
        feat1, 64, (const float*)nullptr, 0, w_off2, b_off2, feat2, 64, 4);

    // 4. offset/mask conv: 64 -> 27  (256 blocks; profiled slot)
    conv3x3_v7<false><<<dim3(4, 16, 4), cblk>>>(
        feat2, 64, (const float*)nullptr, 0, w_om, b_om, omb, 27, 2);

    // 5. deformable conv split over cin (4 x 16 channels) -> partials
    dcn_part<<<dim3(8, 8, 2), 256>>>(x, omb, w_dcn, dp,             0);
    dcn_part<<<dim3(8, 8, 2), 256>>>(x, omb, w_dcn, dp + SPLIT,     16);
    dcn_part<<<dim3(8, 8, 2), 256>>>(x, omb, w_dcn, dp + 2*SPLIT,   32);
    dcn_part<<<dim3(8, 8, 2), 256>>>(x, omb, w_dcn, dp + 3*SPLIT,   48);

    // 5b. epilogue: sum partials + bias + lrelu + 1x1 + lrelu -> d2
    dcn_epilogue<<<dim3(8, 8, 2), 256>>>(dp, b_dcn, w_1x1, b_1x1, d2);

    // 6. final conv: concat(d2, new_inp) (128) -> 64
    conv3x3_v7<false><<<dim3(4, 16, 8), cblk>>>(
        d2, 64, new_inp, 64, w_3x3, b_3x3, out, 64, 4);
}

// round 10
// speedup vs baseline: 1.2076x; 1.2076x over previous
#include <cuda_runtime.h>
#include <cstdint>
#include <math.h>

#define HH 128
#define WW 128
#define HW (128*128)
#define FFT_T 1024

typedef unsigned long long u64;

// ---------------- scratch (device globals; no allocation) ----------------
__device__ float g_feat0[2*128*HW];
__device__ float g_feat1[2*64*HW];
__device__ float g_feat2[2*64*HW];
__device__ float g_om  [2*27*HW];
__device__ float g_d2  [2*64*HW];

__device__ __forceinline__ int brev7(int v) { return (int)(__brev((unsigned)v) >> 25); }

// ---------------- packed fp32x2 helpers (sm_103a FFMA2) ----------------
__device__ __forceinline__ u64 pack2(float v) {
    u64 r; asm("mov.b64 %0, {%1, %1};" : "=l"(r) : "f"(v)); return r;
}
__device__ __forceinline__ u64 pack_pair(float lo, float hi) {
    u64 r; asm("mov.b64 %0, {%1, %2};" : "=l"(r) : "f"(lo), "f"(hi)); return r;
}
__device__ __forceinline__ void unpack2(u64 v, float& lo, float& hi) {
    asm("mov.b64 {%0, %1}, %2;" : "=f"(lo), "=f"(hi) : "l"(v));
}
__device__ __forceinline__ void fma2(u64& d, u64 a, u64 b) {
    asm("fma.rn.f32x2 %0, %1, %2, %0;" : "+l"(d) : "l"(a), "l"(b));
}

// ---------------- cp.async helpers ----------------
__device__ __forceinline__ uint32_t smem_u32(const void* p) {
    uint32_t a;
    asm("{ .reg .u64 t; cvta.to.shared.u64 t, %1; cvt.u32.u64 %0, t; }"
        : "=r"(a) : "l"(p));
    return a;
}
__device__ __forceinline__ void cp_async4(uint32_t saddr, const void* gaddr, int srcsize) {
    asm volatile("cp.async.ca.shared.global [%0], [%1], 4, %2;"
                 :: "r"(saddr), "l"(gaddr), "r"(srcsize));
}
#define CP_COMMIT() asm volatile("cp.async.commit_group;")
#define CP_WAIT(N)  asm volatile("cp.async.wait_group %0;" :: "n"(N))

// =====================================================================
// Kernel 1: packed FFT (z = x + i*x_ref), DIF fwd / DIT inv, fused
// radix-2 stage pairs (4 sync points per 1D pass).
// =====================================================================
template<int STEP>
__device__ __forceinline__ void fft_dif(float* sre, float* sim,
                                        const float* ctab, const float* stab)
{
#pragma unroll
    for (int fp = 0; fp < 3; ++fp) {
        int s  = 6 - 2*fp;          // 6,4,2
        int mh = 1 << (s-1);
        for (int t = threadIdx.x; t < 4096; t += FFT_T) {
            int O = t >> 5, g = t & 31;
            int pos = g & (mh-1);
            int i = ((g >> (s-1)) << (s+1)) + pos;
            int base = (STEP == 1) ? O*128 + i : i*128 + O;
            int d1 = mh*STEP, d2 = 2*mh*STEP, d3 = 3*mh*STEP;
            float a0r=sre[base],    a0i=sim[base];
            float a1r=sre[base+d1], a1i=sim[base+d1];
            float a2r=sre[base+d2], a2i=sim[base+d2];
            float a3r=sre[base+d3], a3i=sim[base+d3];
            int r0 = pos << (6-s);
            float c0=ctab[r0], s0=stab[r0];
            float t0r=a0r+a2r, t0i=a0i+a2i;
            float e2r=a0r-a2r, e2i=a0i-a2i;
            float u2r=c0*e2r - s0*e2i, u2i=c0*e2i + s0*e2r;
            float t1r=a1r+a3r, t1i=a1i+a3i;
            float e3r=a1r-a3r, e3i=a1i-a3i;
            float u3r=s0*e3r + c0*e3i, u3i=s0*e3i - c0*e3r;
            int rr = pos << (7-s);
            float c1=ctab[rr], s1=stab[rr];
            sre[base]    = t0r+t1r;           sim[base]    = t0i+t1i;
            float f1r=t0r-t1r, f1i=t0i-t1i;
            sre[base+d1] = c1*f1r - s1*f1i;   sim[base+d1] = c1*f1i + s1*f1r;
            sre[base+d2] = u2r+u3r;           sim[base+d2] = u2i+u3i;
            float f3r=u2r-u3r, f3i=u2i-u3i;
            sre[base+d3] = c1*f3r - s1*f3i;   sim[base+d3] = c1*f3i + s1*f3r;
        }
        __syncthreads();
    }
    for (int t = threadIdx.x; t < 8192; t += FFT_T) {
        int O = t >> 6, j = t & 63;
        int base = (STEP == 1) ? O*128 + 2*j : (2*j)*128 + O;
        float ar=sre[base], ai=sim[base];
        float br=sre[base+STEP], bi=sim[base+STEP];
        sre[base]=ar+br;      sim[base]=ai+bi;
        sre[base+STEP]=ar-br; sim[base+STEP]=ai-bi;
    }
    __syncthreads();
}

template<int STEP>
__device__ __forceinline__ void fft_dit(float* sre, float* sim,
                                        const float* ctab, const float* stab)
{
    for (int t = threadIdx.x; t < 8192; t += FFT_T) {
        int O = t >> 6, j = t & 63;
        int base = (STEP == 1) ? O*128 + 2*j : (2*j)*128 + O;
        float ar=sre[base], ai=sim[base];
        float br=sre[base+STEP], bi=sim[base+STEP];
        sre[base]=ar+br;      sim[base]=ai+bi;
        sre[base+STEP]=ar-br; sim[base+STEP]=ai-bi;
    }
    __syncthreads();
#pragma unroll
    for (int fp = 0; fp < 3; ++fp) {
        int s = 1 + 2*fp;           // 1,3,5
        int m = 1 << s;
        for (int t = threadIdx.x; t < 4096; t += FFT_T) {
            int O = t >> 5, g = t & 31;
            int pos = g & (m-1);
            int i = ((g >> s) << (s+2)) + pos;
            int base = (STEP == 1) ? O*128 + i : i*128 + O;
            int d1 = m*STEP, d2 = 2*m*STEP, d3 = 3*m*STEP;
            float a0r=sre[base],    a0i=sim[base];
            float a1r=sre[base+d1], a1i=sim[base+d1];
            float a2r=sre[base+d2], a2i=sim[base+d2];
            float a3r=sre[base+d3], a3i=sim[base+d3];
            int r = pos << (6-s);
            float cw=ctab[r], sw=-stab[r];
            float t1r = cw*a1r - sw*a1i, t1i = cw*a1i + sw*a1r;
            float q0r = a0r+t1r, q0i = a0i+t1i;
            float q1r = a0r-t1r, q1i = a0i-t1i;
            float t3r = cw*a3r - sw*a3i, t3i = cw*a3i + sw*a3r;
            float q2r = a2r+t3r, q2i = a2i+t3i;
            float q3r = a2r-t3r, q3i = a2i-t3i;
            int r2 = pos << (5-s);
            float c2=ctab[r2], s2=-stab[r2];
            float u2r = c2*q2r - s2*q2i, u2i = c2*q2i + s2*q2r;
            sre[base]    = q0r+u2r; sim[base]    = q0i+u2i;
            sre[base+d2] = q0r-u2r; sim[base+d2] = q0i-u2i;
            float u3r = -s2*q3r - c2*q3i, u3i = -s2*q3i + c2*q3r;
            sre[base+d1] = q1r+u3r; sim[base+d1] = q1i+u3i;
            sre[base+d3] = q1r-u3r; sim[base+d3] = q1i-u3i;
        }
        __syncthreads();
    }
}

__global__ __launch_bounds__(FFT_T) void fft_phase_kernel(
    const float* __restrict__ x, const float* __restrict__ xref,
    const float* __restrict__ amp, float* __restrict__ feat0)
{
    extern __shared__ float sm[];
    float* sre = sm;
    float* sim = sm + HW;
    __shared__ float ctab[64], stab[64];

    int bc = blockIdx.x;
    const float* srcx = x    + (size_t)bc * HW;
    const float* srcr = xref + (size_t)bc * HW;
    const float* ampp = amp  + (size_t)bc * (HH * 65);
    int tid = threadIdx.x;

    if (tid < 64) {
        float s, c;
        sincospif(-(float)tid / 64.0f, &s, &c);
        ctab[tid] = c; stab[tid] = s;
    }

    for (int i = tid; i < HW; i += FFT_T) {
        sre[i] = srcx[i];
        sim[i] = srcr[i];
    }
    __syncthreads();

    fft_dif<1>(sre, sim, ctab, stab);
    fft_dif<128>(sre, sim, ctab, stab);

    for (int i = tid; i < HW; i += FFT_T) {
        int hr = i >> 7, wr = i & 127;
        int h = brev7(hr), w = brev7(wr);
        int hm = (128 - h) & 127, wm = (128 - w) & 127;
        int pi = (brev7(hm) << 7) | brev7(wm);
        if (i > pi) continue;

        float Zr0 = sre[i],  Zi0 = sim[i];
        float Zr1 = sre[pi], Zi1 = sim[pi];

        float fxr = 0.5f * (Zr0 + Zr1), fxi = 0.5f * (Zi0 - Zi1);
        float frr = 0.5f * (Zi0 + Zi1), fri = 0.5f * (Zr1 - Zr0);

        float m2x = fxr * fxr + fxi * fxi;
        float uxr = 1.f, uxi = 0.f;
        if (m2x > 0.f) { float iv = rsqrtf(m2x); uxr = fxr * iv; uxi = fxi * iv; }
        float m2r = frr * frr + fri * fri;
        float urr = 1.f, uri = 0.f;
        if (m2r > 0.f) { float iv = rsqrtf(m2r); urr = frr * iv; uri = fri * iv; }

        float Gxr, Gxi, Grr, Gri;
        if (w == 0 || w == 64) {
            float a0 = ampp[h * 65 + w];
            float a1 = ampp[hm * 65 + w];
            float ap = 0.5f * (a0 + a1), am = 0.5f * (a0 - a1);
            Gxr = ap * uxr; Gxi = am * uxi;
            Grr = ap * urr; Gri = am * uri;
        } else {
            float a = (w < 64) ? ampp[h * 65 + w] : ampp[hm * 65 + (128 - w)];
            Gxr = a * uxr; Gxi = a * uxi;
            Grr = a * urr; Gri = a * uri;
        }

        sre[i]  = Gxr - Gri;  sim[i]  = Gxi + Grr;
        sre[pi] = Gxr + Gri;  sim[pi] = Grr - Gxi;
    }
    __syncthreads();

    fft_dit<1>(sre, sim, ctab, stab);
    fft_dit<128>(sre, sim, ctab, stab);

    int b  = bc >> 6;
    int ch = bc & 63;
    float* dstx = feat0 + ((size_t)(b * 128 + ch)) * HW;
    float* dstr = feat0 + ((size_t)(b * 128 + 64 + ch)) * HW;
    const float scale = 1.0f / 16384.0f;
    for (int i = tid; i < HW; i += FFT_T) {
        dstx[i] = sre[i] * scale;
        dstr[i] = sim[i] * scale;
    }
}

// =====================================================================
// Kernel 2 (v8): 3x3 conv, packed f32x2, 256 thr (32x8), tile 32x16,
// 2 rows/thread, CB=8 couts -> doubled grids (512 / 256 blocks).
// cp.async double buffering.
// =====================================================================
template<bool DO_LRELU>
__global__ __launch_bounds__(256) void conv3x3_v8(
    const float* __restrict__ in1, int Cin1,
    const float* __restrict__ in2, int Cin2,
    const float* __restrict__ wgt, const float* __restrict__ bias,
    float* __restrict__ out, int Cout, int nblk)
{
    constexpr int CB = 8;
    constexpr int CIN_BLK = 4;
    constexpr int TROW = 18;                     // 16 out rows + 2 halo
    constexpr int TELEM = CIN_BLK * TROW * 34;   // 2448
    constexpr int WELEM = CIN_BLK * 9 * CB;      // 288

    __shared__ __align__(16) float tbuf[2][TELEM];
    __shared__ __align__(16) float wbuf[2][WELEM];

    int tid = threadIdx.y * 32 + threadIdx.x;
    int b   = blockIdx.z / nblk;
    int co0 = (blockIdx.z % nblk) * CB;
    int ty0 = blockIdx.y * 16;
    int tx0 = blockIdx.x * 32;
    int tx = threadIdx.x, ty = threadIdx.y;   // ty 0..7
    int Cin = Cin1 + Cin2;
    int nchunks = Cin / CIN_BLK;

    uint32_t tb_s0 = smem_u32(&tbuf[0][0]);
    uint32_t tb_s1 = smem_u32(&tbuf[1][0]);
    uint32_t wb_s0 = smem_u32(&wbuf[0][0]);
    uint32_t wb_s1 = smem_u32(&wbuf[1][0]);

    u64 a0[4], a1[4];
#pragma unroll
    for (int o = 0; o < 4; ++o) { a0[o] = 0ULL; a1[o] = 0ULL; }

    auto stage = [&](int cin0, uint32_t tb_s, uint32_t wb_s) {
        for (int i = tid; i < TELEM; i += 256) {
            int c = i / (TROW * 34); int rem = i - c * (TROW * 34);
            int r = rem / 34; int col = rem - r * 34;
            int cin = cin0 + c;
            const float* src = (cin < Cin1)
                ? in1 + ((size_t)(b * Cin1 + cin)) * HW
                : in2 + ((size_t)(b * Cin2 + cin - Cin1)) * HW;
            int gy = ty0 - 1 + r, gx = tx0 - 1 + col;
            bool inb = ((unsigned)gy < 128u) && ((unsigned)gx < 128u);
            int cy = min(max(gy, 0), 127), cx = min(max(gx, 0), 127);
            cp_async4(tb_s + i * 4, src + cy * 128 + cx, inb ? 4 : 0);
        }
        for (int i = tid; i < WELEM; i += 256) {      // WELEM=288 > 256: loop!
            int c = i / (9 * CB); int rem = i - c * (9 * CB);
            int k = rem / CB; int o = rem - k * CB;
            int co = min(co0 + o, Cout - 1);
            cp_async4(wb_s + i * 4, &wgt[((size_t)co * Cin + cin0 + c) * 9 + k], 4);
        }
        CP_COMMIT();
    };

    stage(0, tb_s0, wb_s0);

    for (int chunk = 0; chunk < nchunks; ++chunk) {
        int cur = chunk & 1;
        bool hasnext = (chunk + 1 < nchunks);
        if (hasnext)
            stage((chunk + 1) * CIN_BLK, cur ? tb_s0 : tb_s1, cur ? wb_s0 : wb_s1);
        if (hasnext) { CP_WAIT(1); } else { CP_WAIT(0); }
        __syncthreads();

        const float* tb = tbuf[cur];
        const ulonglong2* wb2 = reinterpret_cast<const ulonglong2*>(wbuf[cur]);
#pragma unroll
        for (int c = 0; c < CIN_BLK; ++c) {
            const float* tp = tb + c * (TROW * 34) + ty * 34 + tx;
#pragma unroll
            for (int k = 0; k < 9; ++k) {
                int kyy = k / 3, kxx = k - kyy * 3;
                u64 v0 = pack2(tp[kyy * 34 + kxx]);
                u64 v1 = pack2(tp[(kyy + 8) * 34 + kxx]);
                const ulonglong2* wp = wb2 + (c * 9 + k) * 2;
#pragma unroll
                for (int j = 0; j < 2; ++j) {
                    ulonglong2 wv = wp[j];
                    fma2(a0[2*j],   wv.x, v0); fma2(a0[2*j+1], wv.y, v0);
                    fma2(a1[2*j],   wv.x, v1); fma2(a1[2*j+1], wv.y, v1);
                }
            }
        }
        __syncthreads();
    }

#pragma unroll
    for (int p = 0; p < 4; ++p) {
        float r0lo, r0hi, r1lo, r1hi;
        unpack2(a0[p], r0lo, r0hi);
        unpack2(a1[p], r1lo, r1hi);
#pragma unroll
        for (int e = 0; e < 2; ++e) {
            int o = 2 * p + e;
            if (co0 + o >= Cout) continue;
            float bb = __ldg(&bias[co0 + o]);
            float v0 = (e ? r0hi : r0lo) + bb;
            float v1 = (e ? r1hi : r1lo) + bb;
            if (DO_LRELU) {
                v0 = v0 >= 0.f ? v0 : 0.1f * v0;
                v1 = v1 >= 0.f ? v1 : 0.1f * v1;
            }
            size_t base = ((size_t)(b * Cout + co0 + o)) * HW;
            out[base + (size_t)(ty0 + ty) * 128 + tx0 + tx]     = v0;
            out[base + (size_t)(ty0 + ty + 8) * 128 + tx0 + tx] = v1;
        }
    }
}

// =====================================================================
// Kernel 3 (v2): deformable conv + lrelu + 1x1 + lrelu, packed f32x2.
// 256-thread blocks (16x16 tile). All weights in 160KB dyn smem once.
// =====================================================================
__global__ __launch_bounds__(256) void dcn_kernel_v2(
    const float* __restrict__ x, const float* __restrict__ om,
    const float* __restrict__ wd, const float* __restrict__ bd,
    const float* __restrict__ w1, const float* __restrict__ b1,
    float* __restrict__ out)
{
    extern __shared__ __align__(16) float dsm[];
    float* wdsm = dsm;            // [c][k][o] : 36864 floats
    float* w1sm = dsm + 36864;    // [c][o]    : 4096 floats

    int t = threadIdx.x;
    int b = blockIdx.z;
    int h = blockIdx.y * 16 + (t >> 4);
    int w = blockIdx.x * 16 + (t & 15);

    for (int i = t; i < 36864; i += 256) {
        int c = i / 576; int rem = i - c * 576;
        int k = rem >> 6, o = rem & 63;
        wdsm[i] = wd[((size_t)o * 64 + c) * 9 + k];
    }
    for (int i = t; i < 4096; i += 256) {
        int c = i >> 6, o = i & 63;
        w1sm[i] = w1[o * 64 + c];
    }

    int   iy0[9], ix0[9];
    float wy[9], wx[9], mk[9];
    const float* omb = om + (size_t)b * 27 * HW;
    int pix = h * 128 + w;
#pragma unroll
    for (int k = 0; k < 9; ++k) {
        float dy = omb[(size_t)(2 * k) * HW + pix];
        float dx = omb[(size_t)(2 * k + 1) * HW + pix];
        float mv = omb[(size_t)(18 + k) * HW + pix];
        mk[k] = 1.0f / (1.0f + expf(-mv));
        float py = (float)(h + k / 3 - 1) + dy;
        float px = (float)(w + k % 3 - 1) + dx;
        float fy = floorf(py), fx = floorf(px);
        iy0[k] = (int)fy; ix0[k] = (int)fx;
        wy[k] = py - fy; wx[k] = px - fx;
    }
    __syncthreads();

    u64 acc[32];
#pragma unroll
    for (int o = 0; o < 32; ++o) acc[o] = 0ULL;

    const float* xb = x + (size_t)b * 64 * HW;
    for (int c = 0; c < 64; ++c) {
        const float* xc = xb + (size_t)c * HW;
        const ulonglong2* wbase = reinterpret_cast<const ulonglong2*>(wdsm + c * 576);
#pragma unroll
        for (int k = 0; k < 9; ++k) {
            int y0 = iy0[k], x0 = ix0[k];
            int y1 = y0 + 1, x1 = x0 + 1;
            int cy0 = min(max(y0, 0), 127), cy1 = min(max(y1, 0), 127);
            int cx0 = min(max(x0, 0), 127), cx1 = min(max(x1, 0), 127);
            bool vy0 = (unsigned)y0 < 128u, vy1 = (unsigned)y1 < 128u;
            bool vx0 = (unsigned)x0 < 128u, vx1 = (unsigned)x1 < 128u;
            float g00 = (vy0 && vx0) ? __ldg(&xc[cy0 * 128 + cx0]) : 0.f;
            float g01 = (vy0 && vx1) ? __ldg(&xc[cy0 * 128 + cx1]) : 0.f;
            float g10 = (vy1 && vx0) ? __ldg(&xc[cy1 * 128 + cx0]) : 0.f;
            float g11 = (vy1 && vx1) ? __ldg(&xc[cy1 * 128 + cx1]) : 0.f;
            float wxx = wx[k], wyy = wy[k];
            float top = g00 + (g01 - g00) * wxx;
            float bot = g10 + (g11 - g10) * wxx;
            u64 ss = pack2((top + (bot - top) * wyy) * mk[k]);
            const ulonglong2* wp = wbase + k * 16;
#pragma unroll
            for (int j = 0; j < 16; ++j) {
                ulonglong2 wv = wp[j];
                fma2(acc[2*j],   wv.x, ss);
                fma2(acc[2*j+1], wv.y, ss);
            }
        }
    }

    float av[64];
#pragma unroll
    for (int p = 0; p < 32; ++p) {
        float lo, hi;
        unpack2(acc[p], lo, hi);
        float v0 = lo + __ldg(&bd[2*p]);
        float v1 = hi + __ldg(&bd[2*p+1]);
        av[2*p]   = v0 >= 0.f ? v0 : 0.1f * v0;
        av[2*p+1] = v1 >= 0.f ? v1 : 0.1f * v1;
    }

    float* outb = out + (size_t)b * 64 * HW;
#pragma unroll
    for (int og = 0; og < 4; ++og) {
        u64 acc2[8];
#pragma unroll
        for (int j = 0; j < 8; ++j)
            acc2[j] = pack_pair(__ldg(&b1[og*16 + 2*j]), __ldg(&b1[og*16 + 2*j + 1]));
        for (int c = 0; c < 64; ++c) {
            u64 vv = pack2(av[c]);
            const ulonglong2* wp = reinterpret_cast<const ulonglong2*>(w1sm + c * 64 + og * 16);
#pragma unroll
            for (int j = 0; j < 4; ++j) {
                ulonglong2 wv = wp[j];
                fma2(acc2[2*j],   wv.x, vv);
                fma2(acc2[2*j+1], wv.y, vv);
            }
        }
#pragma unroll
        for (int j = 0; j < 8; ++j) {
            float lo, hi;
            unpack2(acc2[j], lo, hi);
            lo = lo >= 0.f ? lo : 0.1f * lo;
            hi = hi >= 0.f ? hi : 0.1f * hi;
            outb[(size_t)(og * 16 + 2*j) * HW + pix]     = lo;
            outb[(size_t)(og * 16 + 2*j + 1) * HW + pix] = hi;
        }
    }
}

// =====================================================================
// launch
// =====================================================================
extern "C" void kernel_launch(void* const* d_in, const int* in_sizes, int n_in,
                              void* d_out, int out_size)
{
    const float* x       = (const float*)d_in[0];
    const float* x_ref   = (const float*)d_in[1];
    const float* amp     = (const float*)d_in[2];
    const float* new_inp = (const float*)d_in[3];
    const float* w_off1  = (const float*)d_in[4];
    const float* b_off1  = (const float*)d_in[5];
    const float* w_off2  = (const float*)d_in[6];
    const float* b_off2  = (const float*)d_in[7];
    const float* w_om    = (const float*)d_in[8];
    const float* b_om    = (const float*)d_in[9];
    const float* w_dcn   = (const float*)d_in[10];
    const float* b_dcn   = (const float*)d_in[11];
    const float* w_1x1   = (const float*)d_in[12];
    const float* b_1x1   = (const float*)d_in[13];
    const float* w_3x3   = (const float*)d_in[14];
    const float* b_3x3   = (const float*)d_in[15];
    float* out = (float*)d_out;

    float *feat0, *feat1, *feat2, *omb, *d2;
    cudaGetSymbolAddress((void**)&feat0, g_feat0);
    cudaGetSymbolAddress((void**)&feat1, g_feat1);
    cudaGetSymbolAddress((void**)&feat2, g_feat2);
    cudaGetSymbolAddress((void**)&omb,   g_om);
    cudaGetSymbolAddress((void**)&d2,    g_d2);

    cudaFuncSetAttribute(fft_phase_kernel,
                         cudaFuncAttributeMaxDynamicSharedMemorySize, 131072);
    cudaFuncSetAttribute(dcn_kernel_v2,
                         cudaFuncAttributeMaxDynamicSharedMemorySize, 163840);

    // 1. packed FFT phase/amplitude recombination -> feat0
    fft_phase_kernel<<<128, FFT_T, 131072>>>(x, x_ref, amp, feat0);

    dim3 cblk(32, 8);

    // 2. conv_off1: 128 -> 64, lrelu  (512 blocks)
    conv3x3_v8<true><<<dim3(4, 8, 16), cblk>>>(
        feat0, 128, (const float*)nullptr, 0, w_off1, b_off1, feat1, 64, 8);

    // 3. conv_off2: 64 -> 64, lrelu  (512 blocks)
    conv3x3_v8<true><<<dim3(4, 8, 16), cblk>>>(
        feat1, 64, (const float*)nullptr, 0, w_off2, b_off2, feat2, 64, 8);

    // 4. offset/mask conv: 64 -> 27  (256 blocks)
    conv3x3_v8<false><<<dim3(4, 8, 8), cblk>>>(
        feat2, 64, (const float*)nullptr, 0, w_om, b_om, omb, 27, 4);

    // 5. deformable conv + lrelu + 1x1 + lrelu -> d2
    dcn_kernel_v2<<<dim3(8, 8, 2), 256, 163840>>>(
        x, omb, w_dcn, b_dcn, w_1x1, b_1x1, d2);

    // 6. final conv: concat(d2, new_inp) (128) -> 64  (512 blocks)
    conv3x3_v8<false><<<dim3(4, 8, 16), cblk>>>(
        d2, 64, new_inp, 64, w_3x3, b_3x3, out, 64, 8);
}

// round 11
// speedup vs baseline: 1.3031x; 1.0790x over previous
#include <cuda_runtime.h>
#include <cstdint>
#include <math.h>

#define HH 128
#define WW 128
#define HW (128*128)
#define FFT_T 1024

typedef unsigned long long u64;

// ---------------- scratch (device globals; no allocation) ----------------
__device__ float g_feat0[2*128*HW];
__device__ float g_feat1[2*64*HW];
__device__ float g_feat2[2*64*HW];
__device__ float g_om  [2*27*HW];
__device__ float g_d2  [2*64*HW];

__device__ __forceinline__ int brev7(int v) { return (int)(__brev((unsigned)v) >> 25); }

// ---------------- packed fp32x2 helpers (sm_103a FFMA2) ----------------
__device__ __forceinline__ u64 pack2(float v) {
    u64 r; asm("mov.b64 %0, {%1, %1};" : "=l"(r) : "f"(v)); return r;
}
__device__ __forceinline__ u64 pack_pair(float lo, float hi) {
    u64 r; asm("mov.b64 %0, {%1, %2};" : "=l"(r) : "f"(lo), "f"(hi)); return r;
}
__device__ __forceinline__ void unpack2(u64 v, float& lo, float& hi) {
    asm("mov.b64 {%0, %1}, %2;" : "=f"(lo), "=f"(hi) : "l"(v));
}
__device__ __forceinline__ void fma2(u64& d, u64 a, u64 b) {
    asm("fma.rn.f32x2 %0, %1, %2, %0;" : "+l"(d) : "l"(a), "l"(b));
}

// ---------------- cp.async helpers ----------------
__device__ __forceinline__ uint32_t smem_u32(const void* p) {
    uint32_t a;
    asm("{ .reg .u64 t; cvta.to.shared.u64 t, %1; cvt.u32.u64 %0, t; }"
        : "=r"(a) : "l"(p));
    return a;
}
__device__ __forceinline__ void cp_async4(uint32_t saddr, const void* gaddr, int srcsize) {
    asm volatile("cp.async.ca.shared.global [%0], [%1], 4, %2;"
                 :: "r"(saddr), "l"(gaddr), "r"(srcsize));
}
#define CP_COMMIT() asm volatile("cp.async.commit_group;")
#define CP_WAIT(N)  asm volatile("cp.async.wait_group %0;" :: "n"(N))

// =====================================================================
// Kernel 1: packed FFT (z = x + i*x_ref), DIF fwd / DIT inv, fused
// radix-2 stage pairs (4 sync points per 1D pass). Validated R10.
// =====================================================================
template<int STEP>
__device__ __forceinline__ void fft_dif(float* sre, float* sim,
                                        const float* ctab, const float* stab)
{
#pragma unroll
    for (int fp = 0; fp < 3; ++fp) {
        int s  = 6 - 2*fp;          // 6,4,2
        int mh = 1 << (s-1);
        for (int t = threadIdx.x; t < 4096; t += FFT_T) {
            int O = t >> 5, g = t & 31;
            int pos = g & (mh-1);
            int i = ((g >> (s-1)) << (s+1)) + pos;
            int base = (STEP == 1) ? O*128 + i : i*128 + O;
            int d1 = mh*STEP, d2 = 2*mh*STEP, d3 = 3*mh*STEP;
            float a0r=sre[base],    a0i=sim[base];
            float a1r=sre[base+d1], a1i=sim[base+d1];
            float a2r=sre[base+d2], a2i=sim[base+d2];
            float a3r=sre[base+d3], a3i=sim[base+d3];
            int r0 = pos << (6-s);
            float c0=ctab[r0], s0=stab[r0];
            float t0r=a0r+a2r, t0i=a0i+a2i;
            float e2r=a0r-a2r, e2i=a0i-a2i;
            float u2r=c0*e2r - s0*e2i, u2i=c0*e2i + s0*e2r;
            float t1r=a1r+a3r, t1i=a1i+a3i;
            float e3r=a1r-a3r, e3i=a1i-a3i;
            float u3r=s0*e3r + c0*e3i, u3i=s0*e3i - c0*e3r;
            int rr = pos << (7-s);
            float c1=ctab[rr], s1=stab[rr];
            sre[base]    = t0r+t1r;           sim[base]    = t0i+t1i;
            float f1r=t0r-t1r, f1i=t0i-t1i;
            sre[base+d1] = c1*f1r - s1*f1i;   sim[base+d1] = c1*f1i + s1*f1r;
            sre[base+d2] = u2r+u3r;           sim[base+d2] = u2i+u3i;
            float f3r=u2r-u3r, f3i=u2i-u3i;
            sre[base+d3] = c1*f3r - s1*f3i;   sim[base+d3] = c1*f3i + s1*f3r;
        }
        __syncthreads();
    }
    for (int t = threadIdx.x; t < 8192; t += FFT_T) {
        int O = t >> 6, j = t & 63;
        int base = (STEP == 1) ? O*128 + 2*j : (2*j)*128 + O;
        float ar=sre[base], ai=sim[base];
        float br=sre[base+STEP], bi=sim[base+STEP];
        sre[base]=ar+br;      sim[base]=ai+bi;
        sre[base+STEP]=ar-br; sim[base+STEP]=ai-bi;
    }
    __syncthreads();
}

template<int STEP>
__device__ __forceinline__ void fft_dit(float* sre, float* sim,
                                        const float* ctab, const float* stab)
{
    for (int t = threadIdx.x; t < 8192; t += FFT_T) {
        int O = t >> 6, j = t & 63;
        int base = (STEP == 1) ? O*128 + 2*j : (2*j)*128 + O;
        float ar=sre[base], ai=sim[base];
        float br=sre[base+STEP], bi=sim[base+STEP];
        sre[base]=ar+br;      sim[base]=ai+bi;
        sre[base+STEP]=ar-br; sim[base+STEP]=ai-bi;
    }
    __syncthreads();
#pragma unroll
    for (int fp = 0; fp < 3; ++fp) {
        int s = 1 + 2*fp;           // 1,3,5
        int m = 1 << s;
        for (int t = threadIdx.x; t < 4096; t += FFT_T) {
            int O = t >> 5, g = t & 31;
            int pos = g & (m-1);
            int i = ((g >> s) << (s+2)) + pos;
            int base = (STEP == 1) ? O*128 + i : i*128 + O;
            int d1 = m*STEP, d2 = 2*m*STEP, d3 = 3*m*STEP;
            float a0r=sre[base],    a0i=sim[base];
            float a1r=sre[base+d1], a1i=sim[base+d1];
            float a2r=sre[base+d2], a2i=sim[base+d2];
            float a3r=sre[base+d3], a3i=sim[base+d3];
            int r = pos << (6-s);
            float cw=ctab[r], sw=-stab[r];
            float t1r = cw*a1r - sw*a1i, t1i = cw*a1i + sw*a1r;
            float q0r = a0r+t1r, q0i = a0i+t1i;
            float q1r = a0r-t1r, q1i = a0i-t1i;
            float t3r = cw*a3r - sw*a3i, t3i = cw*a3i + sw*a3r;
            float q2r = a2r+t3r, q2i = a2i+t3i;
            float q3r = a2r-t3r, q3i = a2i-t3i;
            int r2 = pos << (5-s);
            float c2=ctab[r2], s2=-stab[r2];
            float u2r = c2*q2r - s2*q2i, u2i = c2*q2i + s2*q2r;
            sre[base]    = q0r+u2r; sim[base]    = q0i+u2i;
            sre[base+d2] = q0r-u2r; sim[base+d2] = q0i-u2i;
            float u3r = -s2*q3r - c2*q3i, u3i = -s2*q3i + c2*q3r;
            sre[base+d1] = q1r+u3r; sim[base+d1] = q1i+u3i;
            sre[base+d3] = q1r-u3r; sim[base+d3] = q1i-u3i;
        }
        __syncthreads();
    }
}

__global__ __launch_bounds__(FFT_T) void fft_phase_kernel(
    const float* __restrict__ x, const float* __restrict__ xref,
    const float* __restrict__ amp, float* __restrict__ feat0)
{
    extern __shared__ float sm[];
    float* sre = sm;
    float* sim = sm + HW;
    __shared__ float ctab[64], stab[64];

    int bc = blockIdx.x;
    const float* srcx = x    + (size_t)bc * HW;
    const float* srcr = xref + (size_t)bc * HW;
    const float* ampp = amp  + (size_t)bc * (HH * 65);
    int tid = threadIdx.x;

    if (tid < 64) {
        float s, c;
        sincospif(-(float)tid / 64.0f, &s, &c);
        ctab[tid] = c; stab[tid] = s;
    }

    for (int i = tid; i < HW; i += FFT_T) {
        sre[i] = srcx[i];
        sim[i] = srcr[i];
    }
    __syncthreads();

    fft_dif<1>(sre, sim, ctab, stab);
    fft_dif<128>(sre, sim, ctab, stab);

    for (int i = tid; i < HW; i += FFT_T) {
        int hr = i >> 7, wr = i & 127;
        int h = brev7(hr), w = brev7(wr);
        int hm = (128 - h) & 127, wm = (128 - w) & 127;
        int pi = (brev7(hm) << 7) | brev7(wm);
        if (i > pi) continue;

        float Zr0 = sre[i],  Zi0 = sim[i];
        float Zr1 = sre[pi], Zi1 = sim[pi];

        float fxr = 0.5f * (Zr0 + Zr1), fxi = 0.5f * (Zi0 - Zi1);
        float frr = 0.5f * (Zi0 + Zi1), fri = 0.5f * (Zr1 - Zr0);

        float m2x = fxr * fxr + fxi * fxi;
        float uxr = 1.f, uxi = 0.f;
        if (m2x > 0.f) { float iv = rsqrtf(m2x); uxr = fxr * iv; uxi = fxi * iv; }
        float m2r = frr * frr + fri * fri;
        float urr = 1.f, uri = 0.f;
        if (m2r > 0.f) { float iv = rsqrtf(m2r); urr = frr * iv; uri = fri * iv; }

        float Gxr, Gxi, Grr, Gri;
        if (w == 0 || w == 64) {
            float a0 = ampp[h * 65 + w];
            float a1 = ampp[hm * 65 + w];
            float ap = 0.5f * (a0 + a1), am = 0.5f * (a0 - a1);
            Gxr = ap * uxr; Gxi = am * uxi;
            Grr = ap * urr; Gri = am * uri;
        } else {
            float a = (w < 64) ? ampp[h * 65 + w] : ampp[hm * 65 + (128 - w)];
            Gxr = a * uxr; Gxi = a * uxi;
            Grr = a * urr; Gri = a * uri;
        }

        sre[i]  = Gxr - Gri;  sim[i]  = Gxi + Grr;
        sre[pi] = Gxr + Gri;  sim[pi] = Grr - Gxi;
    }
    __syncthreads();

    fft_dit<1>(sre, sim, ctab, stab);
    fft_dit<128>(sre, sim, ctab, stab);

    int b  = bc >> 6;
    int ch = bc & 63;
    float* dstx = feat0 + ((size_t)(b * 128 + ch)) * HW;
    float* dstr = feat0 + ((size_t)(b * 128 + 64 + ch)) * HW;
    const float scale = 1.0f / 16384.0f;
    for (int i = tid; i < HW; i += FFT_T) {
        dstx[i] = sre[i] * scale;
        dstr[i] = sim[i] * scale;
    }
}

// =====================================================================
// Kernel 2 (v6b): 3x3 conv, packed f32x2, 256 thr (32x8), tile 32x16,
// 2 rows/thread, CB=16 couts, CIN_BLK=8 (half the barriers of v6),
// cp.async double buffering. R7-proven structure.
// =====================================================================
template<bool DO_LRELU>
__global__ __launch_bounds__(256) void conv3x3_v6b(
    const float* __restrict__ in1, int Cin1,
    const float* __restrict__ in2, int Cin2,
    const float* __restrict__ wgt, const float* __restrict__ bias,
    float* __restrict__ out, int Cout, int nblk)
{
    constexpr int CB = 16;
    constexpr int CIN_BLK = 8;
    constexpr int TROW = 18;                     // 16 out rows + 2 halo
    constexpr int TELEM = CIN_BLK * TROW * 34;   // 4896
    constexpr int WELEM = CIN_BLK * 9 * CB;      // 1152

    __shared__ __align__(16) float tbuf[2][TELEM];
    __shared__ __align__(16) float wbuf[2][WELEM];

    int tid = threadIdx.y * 32 + threadIdx.x;
    int b   = blockIdx.z / nblk;
    int co0 = (blockIdx.z % nblk) * CB;
    int ty0 = blockIdx.y * 16;
    int tx0 = blockIdx.x * 32;
    int tx = threadIdx.x, ty = threadIdx.y;   // ty 0..7
    int Cin = Cin1 + Cin2;
    int nchunks = Cin / CIN_BLK;

    uint32_t tb_s0 = smem_u32(&tbuf[0][0]);
    uint32_t tb_s1 = smem_u32(&tbuf[1][0]);
    uint32_t wb_s0 = smem_u32(&wbuf[0][0]);
    uint32_t wb_s1 = smem_u32(&wbuf[1][0]);

    u64 a0[8], a1[8];
#pragma unroll
    for (int o = 0; o < 8; ++o) { a0[o] = 0ULL; a1[o] = 0ULL; }

    auto stage = [&](int cin0, uint32_t tb_s, uint32_t wb_s) {
        for (int i = tid; i < TELEM; i += 256) {
            int c = i / (TROW * 34); int rem = i - c * (TROW * 34);
            int r = rem / 34; int col = rem - r * 34;
            int cin = cin0 + c;
            const float* src = (cin < Cin1)
                ? in1 + ((size_t)(b * Cin1 + cin)) * HW
                : in2 + ((size_t)(b * Cin2 + cin - Cin1)) * HW;
            int gy = ty0 - 1 + r, gx = tx0 - 1 + col;
            bool inb = ((unsigned)gy < 128u) && ((unsigned)gx < 128u);
            int cy = min(max(gy, 0), 127), cx = min(max(gx, 0), 127);
            cp_async4(tb_s + i * 4, src + cy * 128 + cx, inb ? 4 : 0);
        }
        for (int i = tid; i < WELEM; i += 256) {
            int c = i / (9 * CB); int rem = i - c * (9 * CB);
            int k = rem / CB; int o = rem - k * CB;
            int co = min(co0 + o, Cout - 1);
            cp_async4(wb_s + i * 4, &wgt[((size_t)co * Cin + cin0 + c) * 9 + k], 4);
        }
        CP_COMMIT();
    };

    stage(0, tb_s0, wb_s0);

    for (int chunk = 0; chunk < nchunks; ++chunk) {
        int cur = chunk & 1;
        bool hasnext = (chunk + 1 < nchunks);
        if (hasnext)
            stage((chunk + 1) * CIN_BLK, cur ? tb_s0 : tb_s1, cur ? wb_s0 : wb_s1);
        if (hasnext) { CP_WAIT(1); } else { CP_WAIT(0); }
        __syncthreads();

        const float* tb = tbuf[cur];
        const ulonglong2* wb2 = reinterpret_cast<const ulonglong2*>(wbuf[cur]);
#pragma unroll
        for (int c = 0; c < CIN_BLK; ++c) {
            const float* tp = tb + c * (TROW * 34) + ty * 34 + tx;
#pragma unroll
            for (int k = 0; k < 9; ++k) {
                int kyy = k / 3, kxx = k - kyy * 3;
                u64 v0 = pack2(tp[kyy * 34 + kxx]);
                u64 v1 = pack2(tp[(kyy + 8) * 34 + kxx]);
                const ulonglong2* wp = wb2 + (c * 9 + k) * 4;
#pragma unroll
                for (int j = 0; j < 4; ++j) {
                    ulonglong2 wv = wp[j];
                    fma2(a0[2*j],   wv.x, v0); fma2(a0[2*j+1], wv.y, v0);
                    fma2(a1[2*j],   wv.x, v1); fma2(a1[2*j+1], wv.y, v1);
                }
            }
        }
        __syncthreads();
    }

#pragma unroll
    for (int p = 0; p < 8; ++p) {
        float r0lo, r0hi, r1lo, r1hi;
        unpack2(a0[p], r0lo, r0hi);
        unpack2(a1[p], r1lo, r1hi);
#pragma unroll
        for (int e = 0; e < 2; ++e) {
            int o = 2 * p + e;
            if (co0 + o >= Cout) continue;
            float bb = __ldg(&bias[co0 + o]);
            float v0 = (e ? r0hi : r0lo) + bb;
            float v1 = (e ? r1hi : r1lo) + bb;
            if (DO_LRELU) {
                v0 = v0 >= 0.f ? v0 : 0.1f * v0;
                v1 = v1 >= 0.f ? v1 : 0.1f * v1;
            }
            size_t base = ((size_t)(b * Cout + co0 + o)) * HW;
            out[base + (size_t)(ty0 + ty) * 128 + tx0 + tx]     = v0;
            out[base + (size_t)(ty0 + ty + 8) * 128 + tx0 + tx] = v1;
        }
    }
}

// =====================================================================
// Kernel 3 (v2): deformable conv + lrelu + 1x1 + lrelu, packed f32x2.
// 256-thread blocks (16x16 tile). All weights in 160KB dyn smem once.
// =====================================================================
__global__ __launch_bounds__(256) void dcn_kernel_v2(
    const float* __restrict__ x, const float* __restrict__ om,
    const float* __restrict__ wd, const float* __restrict__ bd,
    const float* __restrict__ w1, const float* __restrict__ b1,
    float* __restrict__ out)
{
    extern __shared__ __align__(16) float dsm[];
    float* wdsm = dsm;            // [c][k][o] : 36864 floats
    float* w1sm = dsm + 36864;    // [c][o]    : 4096 floats

    int t = threadIdx.x;
    int b = blockIdx.z;
    int h = blockIdx.y * 16 + (t >> 4);
    int w = blockIdx.x * 16 + (t & 15);

    for (int i = t; i < 36864; i += 256) {
        int c = i / 576; int rem = i - c * 576;
        int k = rem >> 6, o = rem & 63;
        wdsm[i] = wd[((size_t)o * 64 + c) * 9 + k];
    }
    for (int i = t; i < 4096; i += 256) {
        int c = i >> 6, o = i & 63;
        w1sm[i] = w1[o * 64 + c];
    }

    int   iy0[9], ix0[9];
    float wy[9], wx[9], mk[9];
    const float* omb = om + (size_t)b * 27 * HW;
    int pix = h * 128 + w;
#pragma unroll
    for (int k = 0; k < 9; ++k) {
        float dy = omb[(size_t)(2 * k) * HW + pix];
        float dx = omb[(size_t)(2 * k + 1) * HW + pix];
        float mv = omb[(size_t)(18 + k) * HW + pix];
        mk[k] = 1.0f / (1.0f + expf(-mv));
        float py = (float)(h + k / 3 - 1) + dy;
        float px = (float)(w + k % 3 - 1) + dx;
        float fy = floorf(py), fx = floorf(px);
        iy0[k] = (int)fy; ix0[k] = (int)fx;
        wy[k] = py - fy; wx[k] = px - fx;
    }
    __syncthreads();

    u64 acc[32];
#pragma unroll
    for (int o = 0; o < 32; ++o) acc[o] = 0ULL;

    const float* xb = x + (size_t)b * 64 * HW;
    for (int c = 0; c < 64; ++c) {
        const float* xc = xb + (size_t)c * HW;
        const ulonglong2* wbase = reinterpret_cast<const ulonglong2*>(wdsm + c * 576);
#pragma unroll
        for (int k = 0; k < 9; ++k) {
            int y0 = iy0[k], x0 = ix0[k];
            int y1 = y0 + 1, x1 = x0 + 1;
            int cy0 = min(max(y0, 0), 127), cy1 = min(max(y1, 0), 127);
            int cx0 = min(max(x0, 0), 127), cx1 = min(max(x1, 0), 127);
            bool vy0 = (unsigned)y0 < 128u, vy1 = (unsigned)y1 < 128u;
            bool vx0 = (unsigned)x0 < 128u, vx1 = (unsigned)x1 < 128u;
            float g00 = (vy0 && vx0) ? __ldg(&xc[cy0 * 128 + cx0]) : 0.f;
            float g01 = (vy0 && vx1) ? __ldg(&xc[cy0 * 128 + cx1]) : 0.f;
            float g10 = (vy1 && vx0) ? __ldg(&xc[cy1 * 128 + cx0]) : 0.f;
            float g11 = (vy1 && vx1) ? __ldg(&xc[cy1 * 128 + cx1]) : 0.f;
            float wxx = wx[k], wyy = wy[k];
            float top = g00 + (g01 - g00) * wxx;
            float bot = g10 + (g11 - g10) * wxx;
            u64 ss = pack2((top + (bot - top) * wyy) * mk[k]);
            const ulonglong2* wp = wbase + k * 16;
#pragma unroll
            for (int j = 0; j < 16; ++j) {
                ulonglong2 wv = wp[j];
                fma2(acc[2*j],   wv.x, ss);
                fma2(acc[2*j+1], wv.y, ss);
            }
        }
    }

    float av[64];
#pragma unroll
    for (int p = 0; p < 32; ++p) {
        float lo, hi;
        unpack2(acc[p], lo, hi);
        float v0 = lo + __ldg(&bd[2*p]);
        float v1 = hi + __ldg(&bd[2*p+1]);
        av[2*p]   = v0 >= 0.f ? v0 : 0.1f * v0;
        av[2*p+1] = v1 >= 0.f ? v1 : 0.1f * v1;
    }

    float* outb = out + (size_t)b * 64 * HW;
#pragma unroll
    for (int og = 0; og < 4; ++og) {
        u64 acc2[8];
#pragma unroll
        for (int j = 0; j < 8; ++j)
            acc2[j] = pack_pair(__ldg(&b1[og*16 + 2*j]), __ldg(&b1[og*16 + 2*j + 1]));
        for (int c = 0; c < 64; ++c) {
            u64 vv = pack2(av[c]);
            const ulonglong2* wp = reinterpret_cast<const ulonglong2*>(w1sm + c * 64 + og * 16);
#pragma unroll
            for (int j = 0; j < 4; ++j) {
                ulonglong2 wv = wp[j];
                fma2(acc2[2*j],   wv.x, vv);
                fma2(acc2[2*j+1], wv.y, vv);
            }
        }
#pragma unroll
        for (int j = 0; j < 8; ++j) {
            float lo, hi;
            unpack2(acc2[j], lo, hi);
            lo = lo >= 0.f ? lo : 0.1f * lo;
            hi = hi >= 0.f ? hi : 0.1f * hi;
            outb[(size_t)(og * 16 + 2*j) * HW + pix]     = lo;
            outb[(size_t)(og * 16 + 2*j + 1) * HW + pix] = hi;
        }
    }
}

// =====================================================================
// launch
// =====================================================================
extern "C" void kernel_launch(void* const* d_in, const int* in_sizes, int n_in,
                              void* d_out, int out_size)
{
    const float* x       = (const float*)d_in[0];
    const float* x_ref   = (const float*)d_in[1];
    const float* amp     = (const float*)d_in[2];
    const float* new_inp = (const float*)d_in[3];
    const float* w_off1  = (const float*)d_in[4];
    const float* b_off1  = (const float*)d_in[5];
    const float* w_off2  = (const float*)d_in[6];
    const float* b_off2  = (const float*)d_in[7];
    const float* w_om    = (const float*)d_in[8];
    const float* b_om    = (const float*)d_in[9];
    const float* w_dcn   = (const float*)d_in[10];
    const float* b_dcn   = (const float*)d_in[11];
    const float* w_1x1   = (const float*)d_in[12];
    const float* b_1x1   = (const float*)d_in[13];
    const float* w_3x3   = (const float*)d_in[14];
    const float* b_3x3   = (const float*)d_in[15];
    float* out = (float*)d_out;

    float *feat0, *feat1, *feat2, *omb, *d2;
    cudaGetSymbolAddress((void**)&feat0, g_feat0);
    cudaGetSymbolAddress((void**)&feat1, g_feat1);
    cudaGetSymbolAddress((void**)&feat2, g_feat2);
    cudaGetSymbolAddress((void**)&omb,   g_om);
    cudaGetSymbolAddress((void**)&d2,    g_d2);

    cudaFuncSetAttribute(fft_phase_kernel,
                         cudaFuncAttributeMaxDynamicSharedMemorySize, 131072);
    cudaFuncSetAttribute(dcn_kernel_v2,
                         cudaFuncAttributeMaxDynamicSharedMemorySize, 163840);

    // 1. packed FFT phase/amplitude recombination -> feat0
    fft_phase_kernel<<<128, FFT_T, 131072>>>(x, x_ref, amp, feat0);

    dim3 cblk(32, 8);

    // 2. conv_off1: 128 -> 64, lrelu  (256 blocks, nblk=4)
    conv3x3_v6b<true><<<dim3(4, 8, 8), cblk>>>(
        feat0, 128, (const float*)nullptr, 0, w_off1, b_off1, feat1, 64, 4);

    // 3. conv_off2: 64 -> 64, lrelu  (256 blocks)
    conv3x3_v6b<true><<<dim3(4, 8, 8), cblk>>>(
        feat1, 64, (const float*)nullptr, 0, w_off2, b_off2, feat2, 64, 4);

    // 4. offset/mask conv: 64 -> 27  (128 blocks, nblk=2)
    conv3x3_v6b<false><<<dim3(4, 8, 4), cblk>>>(
        feat2, 64, (const float*)nullptr, 0, w_om, b_om, omb, 27, 2);

    // 5. deformable conv + lrelu + 1x1 + lrelu -> d2
    dcn_kernel_v2<<<dim3(8, 8, 2), 256, 163840>>>(
        x, omb, w_dcn, b_dcn, w_1x1, b_1x1, d2);

    // 6. final conv: concat(d2, new_inp) (128) -> 64  (256 blocks)
    conv3x3_v6b<false><<<dim3(4, 8, 8), cblk>>>(
        d2, 64, new_inp, 64, w_3x3, b_3x3, out, 64, 4);
}

// round 12
// speedup vs baseline: 1.8195x; 1.3963x over previous
#include <cuda_runtime.h>
#include <cstdint>
#include <math.h>

#define HH 128
#define WW 128
#define HW (128*128)
#define FFT_T 1024

typedef unsigned long long u64;

// ---------------- scratch (device globals; no allocation) ----------------
__device__ float g_feat0[2*128*HW];
__device__ float g_feat1[2*64*HW];
__device__ float g_feat2[2*64*HW];
__device__ float g_om  [2*27*HW];
__device__ float g_d2  [2*64*HW];

__device__ __forceinline__ int brev7(int v) { return (int)(__brev((unsigned)v) >> 25); }

// ---------------- packed fp32x2 helpers (sm_103a FFMA2) ----------------
__device__ __forceinline__ u64 pack2(float v) {
    u64 r; asm("mov.b64 %0, {%1, %1};" : "=l"(r) : "f"(v)); return r;
}
__device__ __forceinline__ u64 pack_pair(float lo, float hi) {
    u64 r; asm("mov.b64 %0, {%1, %2};" : "=l"(r) : "f"(lo), "f"(hi)); return r;
}
__device__ __forceinline__ void unpack2(u64 v, float& lo, float& hi) {
    asm("mov.b64 {%0, %1}, %2;" : "=f"(lo), "=f"(hi) : "l"(v));
}
__device__ __forceinline__ void fma2(u64& d, u64 a, u64 b) {
    asm("fma.rn.f32x2 %0, %1, %2, %0;" : "+l"(d) : "l"(a), "l"(b));
}

// ---------------- cp.async helpers ----------------
__device__ __forceinline__ uint32_t smem_u32(const void* p) {
    uint32_t a;
    asm("{ .reg .u64 t; cvta.to.shared.u64 t, %1; cvt.u32.u64 %0, t; }"
        : "=r"(a) : "l"(p));
    return a;
}
__device__ __forceinline__ void cp_async4(uint32_t saddr, const void* gaddr, int srcsize) {
    asm volatile("cp.async.ca.shared.global [%0], [%1], 4, %2;"
                 :: "r"(saddr), "l"(gaddr), "r"(srcsize));
}
#define CP_COMMIT() asm volatile("cp.async.commit_group;")
#define CP_WAIT(N)  asm volatile("cp.async.wait_group %0;" :: "n"(N))

// =====================================================================
// Kernel 1: packed FFT, fused radix-2 stage pairs.
// Column passes (STEP=128) use lane-major-over-columns decomposition:
// O = t & 127, g = t >> 7  -> warp lanes hit 32 consecutive columns,
// stride-1 banks, conflict-free. (R11 had 32-way conflicts here.)
// =====================================================================
template<int STEP>
__device__ __forceinline__ void fft_dif(float* sre, float* sim,
                                        const float* ctab, const float* stab)
{
#pragma unroll
    for (int fp = 0; fp < 3; ++fp) {
        int s  = 6 - 2*fp;          // 6,4,2
        int mh = 1 << (s-1);
        for (int t = threadIdx.x; t < 4096; t += FFT_T) {
            int O, g;
            if (STEP == 1) { O = t >> 5;  g = t & 31; }
            else           { O = t & 127; g = t >> 7; }
            int pos = g & (mh-1);
            int i = ((g >> (s-1)) << (s+1)) + pos;
            int base = (STEP == 1) ? O*128 + i : i*128 + O;
            int d1 = mh*STEP, d2 = 2*mh*STEP, d3 = 3*mh*STEP;
            float a0r=sre[base],    a0i=sim[base];
            float a1r=sre[base+d1], a1i=sim[base+d1];
            float a2r=sre[base+d2], a2i=sim[base+d2];
            float a3r=sre[base+d3], a3i=sim[base+d3];
            int r0 = pos << (6-s);
            float c0=ctab[r0], s0=stab[r0];
            float t0r=a0r+a2r, t0i=a0i+a2i;
            float e2r=a0r-a2r, e2i=a0i-a2i;
            float u2r=c0*e2r - s0*e2i, u2i=c0*e2i + s0*e2r;
            float t1r=a1r+a3r, t1i=a1i+a3i;
            float e3r=a1r-a3r, e3i=a1i-a3i;
            float u3r=s0*e3r + c0*e3i, u3i=s0*e3i - c0*e3r;
            int rr = pos << (7-s);
            float c1=ctab[rr], s1=stab[rr];
            sre[base]    = t0r+t1r;           sim[base]    = t0i+t1i;
            float f1r=t0r-t1r, f1i=t0i-t1i;
            sre[base+d1] = c1*f1r - s1*f1i;   sim[base+d1] = c1*f1i + s1*f1r;
            sre[base+d2] = u2r+u3r;           sim[base+d2] = u2i+u3i;
            float f3r=u2r-u3r, f3i=u2i-u3i;
            sre[base+d3] = c1*f3r - s1*f3i;   sim[base+d3] = c1*f3i + s1*f3r;
        }
        __syncthreads();
    }
    for (int t = threadIdx.x; t < 8192; t += FFT_T) {
        int O, j;
        if (STEP == 1) { O = t >> 6;  j = t & 63; }
        else           { O = t & 127; j = t >> 7; }
        int base = (STEP == 1) ? O*128 + 2*j : (2*j)*128 + O;
        float ar=sre[base], ai=sim[base];
        float br=sre[base+STEP], bi=sim[base+STEP];
        sre[base]=ar+br;      sim[base]=ai+bi;
        sre[base+STEP]=ar-br; sim[base+STEP]=ai-bi;
    }
    __syncthreads();
}

template<int STEP>
__device__ __forceinline__ void fft_dit(float* sre, float* sim,
                                        const float* ctab, const float* stab)
{
    for (int t = threadIdx.x; t < 8192; t += FFT_T) {
        int O, j;
        if (STEP == 1) { O = t >> 6;  j = t & 63; }
        else           { O = t & 127; j = t >> 7; }
        int base = (STEP == 1) ? O*128 + 2*j : (2*j)*128 + O;
        float ar=sre[base], ai=sim[base];
        float br=sre[base+STEP], bi=sim[base+STEP];
        sre[base]=ar+br;      sim[base]=ai+bi;
        sre[base+STEP]=ar-br; sim[base+STEP]=ai-bi;
    }
    __syncthreads();
#pragma unroll
    for (int fp = 0; fp < 3; ++fp) {
        int s = 1 + 2*fp;           // 1,3,5
        int m = 1 << s;
        for (int t = threadIdx.x; t < 4096; t += FFT_T) {
            int O, g;
            if (STEP == 1) { O = t >> 5;  g = t & 31; }
            else           { O = t & 127; g = t >> 7; }
            int pos = g & (m-1);
            int i = ((g >> s) << (s+2)) + pos;
            int base = (STEP == 1) ? O*128 + i : i*128 + O;
            int d1 = m*STEP, d2 = 2*m*STEP, d3 = 3*m*STEP;
            float a0r=sre[base],    a0i=sim[base];
            float a1r=sre[base+d1], a1i=sim[base+d1];
            float a2r=sre[base+d2], a2i=sim[base+d2];
            float a3r=sre[base+d3], a3i=sim[base+d3];
            int r = pos << (6-s);
            float cw=ctab[r], sw=-stab[r];
            float t1r = cw*a1r - sw*a1i, t1i = cw*a1i + sw*a1r;
            float q0r = a0r+t1r, q0i = a0i+t1i;
            float q1r = a0r-t1r, q1i = a0i-t1i;
            float t3r = cw*a3r - sw*a3i, t3i = cw*a3i + sw*a3r;
            float q2r = a2r+t3r, q2i = a2i+t3i;
            float q3r = a2r-t3r, q3i = a2i-t3i;
            int r2 = pos << (5-s);
            float c2=ctab[r2], s2=-stab[r2];
            float u2r = c2*q2r - s2*q2i, u2i = c2*q2i + s2*q2r;
            sre[base]    = q0r+u2r; sim[base]    = q0i+u2i;
            sre[base+d2] = q0r-u2r; sim[base+d2] = q0i-u2i;
            float u3r = -s2*q3r - c2*q3i, u3i = -s2*q3i + c2*q3r;
            sre[base+d1] = q1r+u3r; sim[base+d1] = q1i+u3i;
            sre[base+d3] = q1r-u3r; sim[base+d3] = q1i-u3i;
        }
        __syncthreads();
    }
}

__global__ __launch_bounds__(FFT_T) void fft_phase_kernel(
    const float* __restrict__ x, const float* __restrict__ xref,
    const float* __restrict__ amp, float* __restrict__ feat0)
{
    extern __shared__ float sm[];
    float* sre = sm;
    float* sim = sm + HW;
    __shared__ float ctab[64], stab[64];

    int bc = blockIdx.x;
    const float* srcx = x    + (size_t)bc * HW;
    const float* srcr = xref + (size_t)bc * HW;
    const float* ampp = amp  + (size_t)bc * (HH * 65);
    int tid = threadIdx.x;

    if (tid < 64) {
        float s, c;
        sincospif(-(float)tid / 64.0f, &s, &c);
        ctab[tid] = c; stab[tid] = s;
    }

    for (int i = tid; i < HW; i += FFT_T) {
        sre[i] = srcx[i];
        sim[i] = srcr[i];
    }
    __syncthreads();

    fft_dif<1>(sre, sim, ctab, stab);
    fft_dif<128>(sre, sim, ctab, stab);

    for (int i = tid; i < HW; i += FFT_T) {
        int hr = i >> 7, wr = i & 127;
        int h = brev7(hr), w = brev7(wr);
        int hm = (128 - h) & 127, wm = (128 - w) & 127;
        int pi = (brev7(hm) << 7) | brev7(wm);
        if (i > pi) continue;

        float Zr0 = sre[i],  Zi0 = sim[i];
        float Zr1 = sre[pi], Zi1 = sim[pi];

        float fxr = 0.5f * (Zr0 + Zr1), fxi = 0.5f * (Zi0 - Zi1);
        float frr = 0.5f * (Zi0 + Zi1), fri = 0.5f * (Zr1 - Zr0);

        float m2x = fxr * fxr + fxi * fxi;
        float uxr = 1.f, uxi = 0.f;
        if (m2x > 0.f) { float iv = rsqrtf(m2x); uxr = fxr * iv; uxi = fxi * iv; }
        float m2r = frr * frr + fri * fri;
        float urr = 1.f, uri = 0.f;
        if (m2r > 0.f) { float iv = rsqrtf(m2r); urr = frr * iv; uri = fri * iv; }

        float Gxr, Gxi, Grr, Gri;
        if (w == 0 || w == 64) {
            float a0 = ampp[h * 65 + w];
            float a1 = ampp[hm * 65 + w];
            float ap = 0.5f * (a0 + a1), am = 0.5f * (a0 - a1);
            Gxr = ap * uxr; Gxi = am * uxi;
            Grr = ap * urr; Gri = am * uri;
        } else {
            float a = (w < 64) ? ampp[h * 65 + w] : ampp[hm * 65 + (128 - w)];
            Gxr = a * uxr; Gxi = a * uxi;
            Grr = a * urr; Gri = a * uri;
        }

        sre[i]  = Gxr - Gri;  sim[i]  = Gxi + Grr;
        sre[pi] = Gxr + Gri;  sim[pi] = Grr - Gxi;
    }
    __syncthreads();

    fft_dit<1>(sre, sim, ctab, stab);
    fft_dit<128>(sre, sim, ctab, stab);

    int b  = bc >> 6;
    int ch = bc & 63;
    float* dstx = feat0 + ((size_t)(b * 128 + ch)) * HW;
    float* dstr = feat0 + ((size_t)(b * 128 + 64 + ch)) * HW;
    const float scale = 1.0f / 16384.0f;
    for (int i = tid; i < HW; i += FFT_T) {
        dstx[i] = sre[i] * scale;
        dstr[i] = sim[i] * scale;
    }
}

// =====================================================================
// Kernel 2 (v6b): 3x3 conv, packed f32x2, 256 thr (32x8), tile 32x16,
// 2 rows/thread, CB=16, CIN_BLK=8, cp.async double buffering.
// =====================================================================
template<bool DO_LRELU>
__global__ __launch_bounds__(256) void conv3x3_v6b(
    const float* __restrict__ in1, int Cin1,
    const float* __restrict__ in2, int Cin2,
    const float* __restrict__ wgt, const float* __restrict__ bias,
    float* __restrict__ out, int Cout, int nblk)
{
    constexpr int CB = 16;
    constexpr int CIN_BLK = 8;
    constexpr int TROW = 18;
    constexpr int TELEM = CIN_BLK * TROW * 34;   // 4896
    constexpr int WELEM = CIN_BLK * 9 * CB;      // 1152

    __shared__ __align__(16) float tbuf[2][TELEM];
    __shared__ __align__(16) float wbuf[2][WELEM];

    int tid = threadIdx.y * 32 + threadIdx.x;
    int b   = blockIdx.z / nblk;
    int co0 = (blockIdx.z % nblk) * CB;
    int ty0 = blockIdx.y * 16;
    int tx0 = blockIdx.x * 32;
    int tx = threadIdx.x, ty = threadIdx.y;
    int Cin = Cin1 + Cin2;
    int nchunks = Cin / CIN_BLK;

    uint32_t tb_s0 = smem_u32(&tbuf[0][0]);
    uint32_t tb_s1 = smem_u32(&tbuf[1][0]);
    uint32_t wb_s0 = smem_u32(&wbuf[0][0]);
    uint32_t wb_s1 = smem_u32(&wbuf[1][0]);

    u64 a0[8], a1[8];
#pragma unroll
    for (int o = 0; o < 8; ++o) { a0[o] = 0ULL; a1[o] = 0ULL; }

    auto stage = [&](int cin0, uint32_t tb_s, uint32_t wb_s) {
        for (int i = tid; i < TELEM; i += 256) {
            int c = i / (TROW * 34); int rem = i - c * (TROW * 34);
            int r = rem / 34; int col = rem - r * 34;
            int cin = cin0 + c;
            const float* src = (cin < Cin1)
                ? in1 + ((size_t)(b * Cin1 + cin)) * HW
                : in2 + ((size_t)(b * Cin2 + cin - Cin1)) * HW;
            int gy = ty0 - 1 + r, gx = tx0 - 1 + col;
            bool inb = ((unsigned)gy < 128u) && ((unsigned)gx < 128u);
            int cy = min(max(gy, 0), 127), cx = min(max(gx, 0), 127);
            cp_async4(tb_s + i * 4, src + cy * 128 + cx, inb ? 4 : 0);
        }
        for (int i = tid; i < WELEM; i += 256) {
            int c = i / (9 * CB); int rem = i - c * (9 * CB);
            int k = rem / CB; int o = rem - k * CB;
            int co = min(co0 + o, Cout - 1);
            cp_async4(wb_s + i * 4, &wgt[((size_t)co * Cin + cin0 + c) * 9 + k], 4);
        }
        CP_COMMIT();
    };

    stage(0, tb_s0, wb_s0);

    for (int chunk = 0; chunk < nchunks; ++chunk) {
        int cur = chunk & 1;
        bool hasnext = (chunk + 1 < nchunks);
        if (hasnext)
            stage((chunk + 1) * CIN_BLK, cur ? tb_s0 : tb_s1, cur ? wb_s0 : wb_s1);
        if (hasnext) { CP_WAIT(1); } else { CP_WAIT(0); }
        __syncthreads();

        const float* tb = tbuf[cur];
        const ulonglong2* wb2 = reinterpret_cast<const ulonglong2*>(wbuf[cur]);
#pragma unroll
        for (int c = 0; c < CIN_BLK; ++c) {
            const float* tp = tb + c * (TROW * 34) + ty * 34 + tx;
#pragma unroll
            for (int k = 0; k < 9; ++k) {
                int kyy = k / 3, kxx = k - kyy * 3;
                u64 v0 = pack2(tp[kyy * 34 + kxx]);
                u64 v1 = pack2(tp[(kyy + 8) * 34 + kxx]);
                const ulonglong2* wp = wb2 + (c * 9 + k) * 4;
#pragma unroll
                for (int j = 0; j < 4; ++j) {
                    ulonglong2 wv = wp[j];
                    fma2(a0[2*j],   wv.x, v0); fma2(a0[2*j+1], wv.y, v0);
                    fma2(a1[2*j],   wv.x, v1); fma2(a1[2*j+1], wv.y, v1);
                }
            }
        }
        __syncthreads();
    }

#pragma unroll
    for (int p = 0; p < 8; ++p) {
        float r0lo, r0hi, r1lo, r1hi;
        unpack2(a0[p], r0lo, r0hi);
        unpack2(a1[p], r1lo, r1hi);
#pragma unroll
        for (int e = 0; e < 2; ++e) {
            int o = 2 * p + e;
            if (co0 + o >= Cout) continue;
            float bb = __ldg(&bias[co0 + o]);
            float v0 = (e ? r0hi : r0lo) + bb;
            float v1 = (e ? r1hi : r1lo) + bb;
            if (DO_LRELU) {
                v0 = v0 >= 0.f ? v0 : 0.1f * v0;
                v1 = v1 >= 0.f ? v1 : 0.1f * v1;
            }
            size_t base = ((size_t)(b * Cout + co0 + o)) * HW;
            out[base + (size_t)(ty0 + ty) * 128 + tx0 + tx]     = v0;
            out[base + (size_t)(ty0 + ty + 8) * 128 + tx0 + tx] = v1;
        }
    }
}

// =====================================================================
// Kernel 3 (v2): deformable conv + lrelu + 1x1 + lrelu, packed f32x2.
// =====================================================================
__global__ __launch_bounds__(256) void dcn_kernel_v2(
    const float* __restrict__ x, const float* __restrict__ om,
    const float* __restrict__ wd, const float* __restrict__ bd,
    const float* __restrict__ w1, const float* __restrict__ b1,
    float* __restrict__ out)
{
    extern __shared__ __align__(16) float dsm[];
    float* wdsm = dsm;            // [c][k][o] : 36864 floats
    float* w1sm = dsm + 36864;    // [c][o]    : 4096 floats

    int t = threadIdx.x;
    int b = blockIdx.z;
    int h = blockIdx.y * 16 + (t >> 4);
    int w = blockIdx.x * 16 + (t & 15);

    for (int i = t; i < 36864; i += 256) {
        int c = i / 576; int rem = i - c * 576;
        int k = rem >> 6, o = rem & 63;
        wdsm[i] = wd[((size_t)o * 64 + c) * 9 + k];
    }
    for (int i = t; i < 4096; i += 256) {
        int c = i >> 6, o = i & 63;
        w1sm[i] = w1[o * 64 + c];
    }

    int   iy0[9], ix0[9];
    float wy[9], wx[9], mk[9];
    const float* omb = om + (size_t)b * 27 * HW;
    int pix = h * 128 + w;
#pragma unroll
    for (int k = 0; k < 9; ++k) {
        float dy = omb[(size_t)(2 * k) * HW + pix];
        float dx = omb[(size_t)(2 * k + 1) * HW + pix];
        float mv = omb[(size_t)(18 + k) * HW + pix];
        mk[k] = 1.0f / (1.0f + expf(-mv));
        float py = (float)(h + k / 3 - 1) + dy;
        float px = (float)(w + k % 3 - 1) + dx;
        float fy = floorf(py), fx = floorf(px);
        iy0[k] = (int)fy; ix0[k] = (int)fx;
        wy[k] = py - fy; wx[k] = px - fx;
    }
    __syncthreads();

    u64 acc[32];
#pragma unroll
    for (int o = 0; o < 32; ++o) acc[o] = 0ULL;

    const float* xb = x + (size_t)b * 64 * HW;
    for (int c = 0; c < 64; ++c) {
        const float* xc = xb + (size_t)c * HW;
        const ulonglong2* wbase = reinterpret_cast<const ulonglong2*>(wdsm + c * 576);
#pragma unroll
        for (int k = 0; k < 9; ++k) {
            int y0 = iy0[k], x0 = ix0[k];
            int y1 = y0 + 1, x1 = x0 + 1;
            int cy0 = min(max(y0, 0), 127), cy1 = min(max(y1, 0), 127);
            int cx0 = min(max(x0, 0), 127), cx1 = min(max(x1, 0), 127);
            bool vy0 = (unsigned)y0 < 128u, vy1 = (unsigned)y1 < 128u;
            bool vx0 = (unsigned)x0 < 128u, vx1 = (unsigned)x1 < 128u;
            float g00 = (vy0 && vx0) ? __ldg(&xc[cy0 * 128 + cx0]) : 0.f;
            float g01 = (vy0 && vx1) ? __ldg(&xc[cy0 * 128 + cx1]) : 0.f;
            float g10 = (vy1 && vx0) ? __ldg(&xc[cy1 * 128 + cx0]) : 0.f;
            float g11 = (vy1 && vx1) ? __ldg(&xc[cy1 * 128 + cx1]) : 0.f;
            float wxx = wx[k], wyy = wy[k];
            float top = g00 + (g01 - g00) * wxx;
            float bot = g10 + (g11 - g10) * wxx;
            u64 ss = pack2((top + (bot - top) * wyy) * mk[k]);
            const ulonglong2* wp = wbase + k * 16;
#pragma unroll
            for (int j = 0; j < 16; ++j) {
                ulonglong2 wv = wp[j];
                fma2(acc[2*j],   wv.x, ss);
                fma2(acc[2*j+1], wv.y, ss);
            }
        }
    }

    float av[64];
#pragma unroll
    for (int p = 0; p < 32; ++p) {
        float lo, hi;
        unpack2(acc[p], lo, hi);
        float v0 = lo + __ldg(&bd[2*p]);
        float v1 = hi + __ldg(&bd[2*p+1]);
        av[2*p]   = v0 >= 0.f ? v0 : 0.1f * v0;
        av[2*p+1] = v1 >= 0.f ? v1 : 0.1f * v1;
    }

    float* outb = out + (size_t)b * 64 * HW;
#pragma unroll
    for (int og = 0; og < 4; ++og) {
        u64 acc2[8];
#pragma unroll
        for (int j = 0; j < 8; ++j)
            acc2[j] = pack_pair(__ldg(&b1[og*16 + 2*j]), __ldg(&b1[og*16 + 2*j + 1]));
        for (int c = 0; c < 64; ++c) {
            u64 vv = pack2(av[c]);
            const ulonglong2* wp = reinterpret_cast<const ulonglong2*>(w1sm + c * 64 + og * 16);
#pragma unroll
            for (int j = 0; j < 4; ++j) {
                ulonglong2 wv = wp[j];
                fma2(acc2[2*j],   wv.x, vv);
                fma2(acc2[2*j+1], wv.y, vv);
            }
        }
#pragma unroll
        for (int j = 0; j < 8; ++j) {
            float lo, hi;
            unpack2(acc2[j], lo, hi);
            lo = lo >= 0.f ? lo : 0.1f * lo;
            hi = hi >= 0.f ? hi : 0.1f * hi;
            outb[(size_t)(og * 16 + 2*j) * HW + pix]     = lo;
            outb[(size_t)(og * 16 + 2*j + 1) * HW + pix] = hi;
        }
    }
}

// =====================================================================
// launch
// =====================================================================
extern "C" void kernel_launch(void* const* d_in, const int* in_sizes, int n_in,
                              void* d_out, int out_size)
{
    const float* x       = (const float*)d_in[0];
    const float* x_ref   = (const float*)d_in[1];
    const float* amp     = (const float*)d_in[2];
    const float* new_inp = (const float*)d_in[3];
    const float* w_off1  = (const float*)d_in[4];
    const float* b_off1  = (const float*)d_in[5];
    const float* w_off2  = (const float*)d_in[6];
    const float* b_off2  = (const float*)d_in[7];
    const float* w_om    = (const float*)d_in[8];
    const float* b_om    = (const float*)d_in[9];
    const float* w_dcn   = (const float*)d_in[10];
    const float* b_dcn   = (const float*)d_in[11];
    const float* w_1x1   = (const float*)d_in[12];
    const float* b_1x1   = (const float*)d_in[13];
    const float* w_3x3   = (const float*)d_in[14];
    const float* b_3x3   = (const float*)d_in[15];
    float* out = (float*)d_out;

    float *feat0, *feat1, *feat2, *omb, *d2;
    cudaGetSymbolAddress((void**)&feat0, g_feat0);
    cudaGetSymbolAddress((void**)&feat1, g_feat1);
    cudaGetSymbolAddress((void**)&feat2, g_feat2);
    cudaGetSymbolAddress((void**)&omb,   g_om);
    cudaGetSymbolAddress((void**)&d2,    g_d2);

    cudaFuncSetAttribute(fft_phase_kernel,
                         cudaFuncAttributeMaxDynamicSharedMemorySize, 131072);
    cudaFuncSetAttribute(dcn_kernel_v2,
                         cudaFuncAttributeMaxDynamicSharedMemorySize, 163840);

    // 1. packed FFT phase/amplitude recombination -> feat0
    fft_phase_kernel<<<128, FFT_T, 131072>>>(x, x_ref, amp, feat0);

    dim3 cblk(32, 8);

    // 2. conv_off1: 128 -> 64, lrelu  (256 blocks)
    conv3x3_v6b<true><<<dim3(4, 8, 8), cblk>>>(
        feat0, 128, (const float*)nullptr, 0, w_off1, b_off1, feat1, 64, 4);

    // 3. conv_off2: 64 -> 64, lrelu  (256 blocks)
    conv3x3_v6b<true><<<dim3(4, 8, 8), cblk>>>(
        feat1, 64, (const float*)nullptr, 0, w_off2, b_off2, feat2, 64, 4);

    // 4. offset/mask conv: 64 -> 27  (128 blocks)
    conv3x3_v6b<false><<<dim3(4, 8, 4), cblk>>>(
        feat2, 64, (const float*)nullptr, 0, w_om, b_om, omb, 27, 2);

    // 5. deformable conv + lrelu + 1x1 + lrelu -> d2
    dcn_kernel_v2<<<dim3(8, 8, 2), 256, 163840>>>(
        x, omb, w_dcn, b_dcn, w_1x1, b_1x1, d2);

    // 6. final conv: concat(d2, new_inp) (128) -> 64  (256 blocks)
    conv3x3_v6b<false><<<dim3(4, 8, 8), cblk>>>(
        d2, 64, new_inp, 64, w_3x3, b_3x3, out, 64, 4);
}